// round 2
// baseline (speedup 1.0000x reference)
#include <cuda_runtime.h>
#include <math.h>

#define MTOK 16384
#define NOUT 512
#define KIN  1024
#define NTASKS 3

// Scratch (device globals per allocation-guard rules):
// S[e][b][o]: shared-expert outputs (relu applied), e=0..3, input = task 0
// T[j][b][o]: task-expert outputs, j = t*2+e
// G[t][b][e]: softmaxed gates (6 per token)
__device__ float g_S[(size_t)4 * MTOK * NOUT];
__device__ float g_T[(size_t)6 * MTOK * NOUT];
__device__ float g_G[(size_t)NTASKS * MTOK * 6];

// ---------------------------------------------------------------------------
// GEMM: out = relu(A[16384x1024] @ W[1024x512] + bias), one expert per blockIdx.z
// 128x128x8 tiling, 256 threads, 8x8 per-thread microtile, double-buffered smem
// ---------------------------------------------------------------------------
__global__ __launch_bounds__(256, 2)
void gemm_relu_kernel(const float* __restrict__ task_inputs,
                      const float* __restrict__ shared_W,
                      const float* __restrict__ shared_b,
                      const float* __restrict__ task_W,
                      const float* __restrict__ task_b)
{
    constexpr int M = MTOK, N = NOUT, K = KIN;
    const int z = blockIdx.z;
    const float* A;
    const float* W;
    const float* bias;
    float* out;
    if (z < 4) {
        A    = task_inputs;                       // shared experts see task 0
        W    = shared_W + (size_t)z * K * N;
        bias = shared_b + z * N;
        out  = g_S + (size_t)z * M * N;
    } else {
        const int j = z - 4;
        const int t = j >> 1;
        A    = task_inputs + (size_t)t * M * K;
        W    = task_W + (size_t)j * K * N;
        bias = task_b + j * N;
        out  = g_T + (size_t)j * M * N;
    }

    __shared__ float As[2][8][128];   // [buf][k][m] (transposed)
    __shared__ float Bs[2][8][128];   // [buf][k][n]

    const int tid = threadIdx.x;
    const int bm0 = blockIdx.y * 128;
    const int bn0 = blockIdx.x * 128;

    // global->smem load assignments
    const int arow = tid >> 1;            // 0..127
    const int acg  = (tid & 1) * 4;       // 0 or 4 (k offset)
    const int brow = tid >> 5;            // 0..7   (k row)
    const int bcol = (tid & 31) * 4;      // 0..124 (n col)

    // compute-thread mapping: warps 4x2, lanes 4x8, split 4+4 frags
    const int warp = tid >> 5;
    const int lane = tid & 31;
    const int wm = warp & 3;              // 0..3
    const int wn = warp >> 2;             // 0..1
    const int lm = lane >> 3;             // 0..3
    const int ln = lane & 7;              // 0..7
    const int am0  = wm * 32 + lm * 4;    // + {0..3} and {16..19}
    const int bn0w = wn * 64 + ln * 4;    // + {0..3} and {32..35}

    float acc[8][8];
    #pragma unroll
    for (int i = 0; i < 8; i++)
        #pragma unroll
        for (int j = 0; j < 8; j++) acc[i][j] = 0.f;

    const float* Aptr = A + (size_t)(bm0 + arow) * K + acg;
    const float* Wptr = W + (size_t)brow * N + bn0 + bcol;

    // prologue: stage tile 0
    {
        float4 pa = *(const float4*)Aptr;
        float4 pb = *(const float4*)Wptr;
        As[0][acg + 0][arow] = pa.x;
        As[0][acg + 1][arow] = pa.y;
        As[0][acg + 2][arow] = pa.z;
        As[0][acg + 3][arow] = pa.w;
        *(float4*)&Bs[0][brow][bcol] = pb;
    }
    __syncthreads();

    constexpr int NK = K / 8;   // 128 k-tiles
    for (int kt = 0; kt < NK; kt++) {
        const int cur = kt & 1;
        float4 pa, pb;
        const bool more = (kt + 1 < NK);
        if (more) {
            pa = *(const float4*)(Aptr + (kt + 1) * 8);
            pb = *(const float4*)(Wptr + (size_t)(kt + 1) * 8 * N);
        }
        #pragma unroll
        for (int kk = 0; kk < 8; kk++) {
            float a[8], b[8];
            float4 t0 = *(const float4*)&As[cur][kk][am0];
            float4 t1 = *(const float4*)&As[cur][kk][am0 + 16];
            float4 t2 = *(const float4*)&Bs[cur][kk][bn0w];
            float4 t3 = *(const float4*)&Bs[cur][kk][bn0w + 32];
            a[0] = t0.x; a[1] = t0.y; a[2] = t0.z; a[3] = t0.w;
            a[4] = t1.x; a[5] = t1.y; a[6] = t1.z; a[7] = t1.w;
            b[0] = t2.x; b[1] = t2.y; b[2] = t2.z; b[3] = t2.w;
            b[4] = t3.x; b[5] = t3.y; b[6] = t3.z; b[7] = t3.w;
            #pragma unroll
            for (int i = 0; i < 8; i++)
                #pragma unroll
                for (int j = 0; j < 8; j++)
                    acc[i][j] = fmaf(a[i], b[j], acc[i][j]);
        }
        if (more) {
            const int nx = cur ^ 1;
            As[nx][acg + 0][arow] = pa.x;
            As[nx][acg + 1][arow] = pa.y;
            As[nx][acg + 2][arow] = pa.z;
            As[nx][acg + 3][arow] = pa.w;
            *(float4*)&Bs[nx][brow][bcol] = pb;
        }
        __syncthreads();
    }

    // epilogue: + bias, relu, store
    float bv[8];
    #pragma unroll
    for (int j = 0; j < 8; j++) {
        int nc = bn0 + bn0w + ((j >> 2) * 32) + (j & 3);
        bv[j] = bias[nc];
    }
    #pragma unroll
    for (int i = 0; i < 8; i++) {
        const int m = bm0 + am0 + ((i >> 2) * 16) + (i & 3);
        float* orow = out + (size_t)m * N + bn0 + bn0w;
        float4 v0, v1;
        v0.x = fmaxf(acc[i][0] + bv[0], 0.f);
        v0.y = fmaxf(acc[i][1] + bv[1], 0.f);
        v0.z = fmaxf(acc[i][2] + bv[2], 0.f);
        v0.w = fmaxf(acc[i][3] + bv[3], 0.f);
        v1.x = fmaxf(acc[i][4] + bv[4], 0.f);
        v1.y = fmaxf(acc[i][5] + bv[5], 0.f);
        v1.z = fmaxf(acc[i][6] + bv[6], 0.f);
        v1.w = fmaxf(acc[i][7] + bv[7], 0.f);
        *(float4*)orow        = v0;
        *(float4*)(orow + 32) = v1;
    }
}

// ---------------------------------------------------------------------------
// Gates: logits = x_t @ gate_W[t] + gate_b[t]; softmax over 6 experts
// CTA = 128 threads, 32 tokens; gate_W[t] staged in smem (padded to 8 cols)
// ---------------------------------------------------------------------------
__global__ __launch_bounds__(128)
void gate_kernel(const float* __restrict__ task_inputs,
                 const float* __restrict__ gate_W,
                 const float* __restrict__ gate_b)
{
    __shared__ float Wg[KIN][8];
    const int t = blockIdx.y;
    for (int i = threadIdx.x; i < KIN * 6; i += 128) {
        Wg[i / 6][i % 6] = gate_W[(size_t)t * KIN * 6 + i];
    }
    __syncthreads();

    const int warp = threadIdx.x >> 5;
    const int lane = threadIdx.x & 31;
    const int tok0 = blockIdx.x * 32 + warp * 8;

    float gb[6];
    #pragma unroll
    for (int e = 0; e < 6; e++) gb[e] = gate_b[t * 6 + e];

    for (int w = 0; w < 8; w++) {
        const int b = tok0 + w;
        const float* x = task_inputs + ((size_t)t * MTOK + b) * KIN;
        float s0 = 0.f, s1 = 0.f, s2 = 0.f, s3 = 0.f, s4 = 0.f, s5 = 0.f;
        for (int k = lane; k < KIN; k += 32) {
            float xv = x[k];
            float4 w0 = *(const float4*)&Wg[k][0];
            float2 w1 = *(const float2*)&Wg[k][4];
            s0 = fmaf(xv, w0.x, s0);
            s1 = fmaf(xv, w0.y, s1);
            s2 = fmaf(xv, w0.z, s2);
            s3 = fmaf(xv, w0.w, s3);
            s4 = fmaf(xv, w1.x, s4);
            s5 = fmaf(xv, w1.y, s5);
        }
        #pragma unroll
        for (int off = 16; off > 0; off >>= 1) {
            s0 += __shfl_xor_sync(0xffffffffu, s0, off);
            s1 += __shfl_xor_sync(0xffffffffu, s1, off);
            s2 += __shfl_xor_sync(0xffffffffu, s2, off);
            s3 += __shfl_xor_sync(0xffffffffu, s3, off);
            s4 += __shfl_xor_sync(0xffffffffu, s4, off);
            s5 += __shfl_xor_sync(0xffffffffu, s5, off);
        }
        if (lane == 0) {
            float l[6] = { s0 + gb[0], s1 + gb[1], s2 + gb[2],
                           s3 + gb[3], s4 + gb[4], s5 + gb[5] };
            float mx = l[0];
            #pragma unroll
            for (int e = 1; e < 6; e++) mx = fmaxf(mx, l[e]);
            float sum = 0.f;
            #pragma unroll
            for (int e = 0; e < 6; e++) { l[e] = __expf(l[e] - mx); sum += l[e]; }
            float inv = 1.f / sum;
            float* gp = g_G + ((size_t)t * MTOK + b) * 6;
            #pragma unroll
            for (int e = 0; e < 6; e++) gp[e] = l[e] * inv;
        }
    }
}

// ---------------------------------------------------------------------------
// Combine: out[t,b,:] = sum_{e<4} G[t,b,e]*S[e,b,:] + sum_{e<2} G[t,b,4+e]*T[2t+e,b,:]
// ---------------------------------------------------------------------------
__global__ __launch_bounds__(256)
void combine_kernel(float* __restrict__ out)
{
    const size_t idx = (size_t)blockIdx.x * 256 + threadIdx.x;   // float4 index
    const size_t total = (size_t)NTASKS * MTOK * NOUT / 4;
    if (idx >= total) return;
    const int o4 = (int)(idx & (NOUT / 4 - 1));   // 0..127
    const size_t tb = idx >> 7;                   // t*MTOK + b
    const int t = (int)(tb / MTOK);
    const int b = (int)(tb & (MTOK - 1));

    const float* g = g_G + tb * 6;
    float ge[6];
    #pragma unroll
    for (int e = 0; e < 6; e++) ge[e] = g[e];

    float4 r = make_float4(0.f, 0.f, 0.f, 0.f);
    #pragma unroll
    for (int e = 0; e < 4; e++) {
        const float4 s = *(const float4*)&g_S[(((size_t)e * MTOK) + b) * NOUT + o4 * 4];
        r.x = fmaf(ge[e], s.x, r.x);
        r.y = fmaf(ge[e], s.y, r.y);
        r.z = fmaf(ge[e], s.z, r.z);
        r.w = fmaf(ge[e], s.w, r.w);
    }
    #pragma unroll
    for (int e = 0; e < 2; e++) {
        const float4 s = *(const float4*)&g_T[(((size_t)(t * 2 + e) * MTOK) + b) * NOUT + o4 * 4];
        r.x = fmaf(ge[4 + e], s.x, r.x);
        r.y = fmaf(ge[4 + e], s.y, r.y);
        r.z = fmaf(ge[4 + e], s.z, r.z);
        r.w = fmaf(ge[4 + e], s.w, r.w);
    }
    *(float4*)(out + idx * 4) = r;
}

// ---------------------------------------------------------------------------
extern "C" void kernel_launch(void* const* d_in, const int* in_sizes, int n_in,
                              void* d_out, int out_size)
{
    const float* task_inputs = (const float*)d_in[0];
    const float* shared_W    = (const float*)d_in[1];
    const float* shared_b    = (const float*)d_in[2];
    const float* task_W      = (const float*)d_in[3];
    const float* task_b      = (const float*)d_in[4];
    const float* gate_W      = (const float*)d_in[5];
    const float* gate_b      = (const float*)d_in[6];
    float* out = (float*)d_out;

    // 1) gates (independent of GEMMs)
    dim3 ggrid(MTOK / 32, NTASKS);
    gate_kernel<<<ggrid, 128>>>(task_inputs, gate_W, gate_b);

    // 2) all 10 unique expert GEMMs (4 shared + 6 task) in one grid
    dim3 grid(NOUT / 128, MTOK / 128, 10);
    gemm_relu_kernel<<<grid, 256>>>(task_inputs, shared_W, shared_b, task_W, task_b);

    // 3) gated combine
    const size_t total4 = (size_t)NTASKS * MTOK * NOUT / 4;
    combine_kernel<<<(unsigned)((total4 + 255) / 256), 256>>>(out);
}

// round 4
// speedup vs baseline: 1.6784x; 1.6784x over previous
#include <cuda_runtime.h>
#include <cuda_bf16.h>
#include <cstdint>
#include <math.h>

#define MTOK 16384
#define NOUT 512
#define KIN  1024
#define NTASKS 3
#define NEXP 10

// ---------------- scratch (device globals; no allocations allowed) ----------
__device__ float g_S[(size_t)4 * MTOK * NOUT];            // shared-expert outs
__device__ float g_T[(size_t)6 * MTOK * NOUT];            // task-expert outs
__device__ float g_G[(size_t)NTASKS * MTOK * 6];          // softmaxed gates
__device__ __nv_bfloat16 g_Wh[(size_t)NEXP * NOUT * KIN]; // W^T hi, [e][n][k]
__device__ __nv_bfloat16 g_Wl[(size_t)NEXP * NOUT * KIN]; // W^T lo

// ---------------- helpers ----------------------------------------------------
__device__ __forceinline__ uint32_t smem_u32(const void* p) {
    uint32_t a;
    asm("{ .reg .u64 t; cvta.to.shared.u64 t, %1; cvt.u32.u64 %0, t; }"
        : "=r"(a) : "l"(p));
    return a;
}
__device__ __forceinline__ uint32_t SW(uint32_t o) { return o ^ ((o >> 3) & 0x70); }

__device__ __forceinline__ void cp_async16(uint32_t dst, const void* src) {
    asm volatile("cp.async.cg.shared.global [%0], [%1], 16;"
                 :: "r"(dst), "l"(src) : "memory");
}
#define CP_COMMIT() asm volatile("cp.async.commit_group;" ::: "memory")
#define CP_WAIT0()  asm volatile("cp.async.wait_group 0;" ::: "memory")

__device__ __forceinline__ void ldm_x4(uint32_t* r, uint32_t addr) {
    asm volatile("ldmatrix.sync.aligned.m8n8.x4.shared.b16 {%0,%1,%2,%3}, [%4];"
                 : "=r"(r[0]), "=r"(r[1]), "=r"(r[2]), "=r"(r[3]) : "r"(addr));
}
__device__ __forceinline__ void ldm_x2(uint32_t* r, uint32_t addr) {
    asm volatile("ldmatrix.sync.aligned.m8n8.x2.shared.b16 {%0,%1}, [%2];"
                 : "=r"(r[0]), "=r"(r[1]) : "r"(addr));
}
__device__ __forceinline__ void mma16816(float* c, const uint32_t* a, const uint32_t* b) {
    asm volatile("mma.sync.aligned.m16n8k16.row.col.f32.bf16.bf16.f32 "
                 "{%0,%1,%2,%3}, {%4,%5,%6,%7}, {%8,%9}, {%0,%1,%2,%3};"
                 : "+f"(c[0]), "+f"(c[1]), "+f"(c[2]), "+f"(c[3])
                 : "r"(a[0]), "r"(a[1]), "r"(a[2]), "r"(a[3]), "r"(b[0]), "r"(b[1]));
}

// convert 8 fp32 -> 8 bf16 hi + 8 bf16 lo (packed x2)
__device__ __forceinline__ void cvt8(const float* f, uint4& h, uint4& l) {
    uint32_t hh[4], ll[4];
    #pragma unroll
    for (int i = 0; i < 4; i++) {
        float a = f[2 * i], b = f[2 * i + 1];
        __nv_bfloat16 ah = __float2bfloat16(a);
        __nv_bfloat16 bh = __float2bfloat16(b);
        __nv_bfloat16 al = __float2bfloat16(a - __bfloat162float(ah));
        __nv_bfloat16 bl = __float2bfloat16(b - __bfloat162float(bh));
        __nv_bfloat162 hv; hv.x = ah; hv.y = bh;
        __nv_bfloat162 lv; lv.x = al; lv.y = bl;
        hh[i] = *reinterpret_cast<uint32_t*>(&hv);
        ll[i] = *reinterpret_cast<uint32_t*>(&lv);
    }
    h = make_uint4(hh[0], hh[1], hh[2], hh[3]);
    l = make_uint4(ll[0], ll[1], ll[2], ll[3]);
}

// ---------------- W prep: transpose + bf16 hi/lo split ----------------------
__global__ __launch_bounds__(256)
void wprep_kernel(const float* __restrict__ shared_W, const float* __restrict__ task_W)
{
    __shared__ float tile[32][33];
    const int e = blockIdx.z;
    const float* W = (e < 4) ? shared_W + (size_t)e * KIN * NOUT
                             : task_W + (size_t)(e - 4) * KIN * NOUT;
    const int k0 = blockIdx.x * 32, n0 = blockIdx.y * 32;
    const int tx = threadIdx.x & 31, ty = threadIdx.x >> 5;

    #pragma unroll
    for (int i = 0; i < 4; i++)
        tile[ty + i * 8][tx] = W[(size_t)(k0 + ty + i * 8) * NOUT + n0 + tx];
    __syncthreads();
    #pragma unroll
    for (int i = 0; i < 4; i++) {
        float v = tile[tx][ty + i * 8];
        __nv_bfloat16 hi = __float2bfloat16(v);
        __nv_bfloat16 lo = __float2bfloat16(v - __bfloat162float(hi));
        size_t idx = ((size_t)e * NOUT + (n0 + ty + i * 8)) * KIN + k0 + tx;
        g_Wh[idx] = hi;
        g_Wl[idx] = lo;
    }
}

// ---------------- HMMA GEMM: 128x128 CTA tile, K chunks of 64 ---------------
// smem per stage (64KB): Ah[128][64]bf16 @0, Al @16K, Bh[128n][64k]bf16 @32K, Bl @48K
#define ST_AH 0
#define ST_AL 16384
#define ST_BH 32768
#define ST_BL 49152
#define STAGE 65536
#define SMEM_BYTES (2 * STAGE + 1024)
#define NKT (KIN / 64)   // 16

__global__ __launch_bounds__(256, 1)
void gemm_mma_kernel(const float* __restrict__ task_inputs,
                     const float* __restrict__ shared_b,
                     const float* __restrict__ task_b)
{
    extern __shared__ char dsm[];
    __shared__ float sbias[128];

    const uint32_t raw = smem_u32(dsm);
    const uint32_t sb = (raw + 1023u) & ~1023u;
    char* base = dsm + (sb - raw);

    const int tid = threadIdx.x;
    const int warp = tid >> 5;
    const int lane = tid & 31;

    const int z = blockIdx.z;
    const int bm0 = blockIdx.y * 128;
    const int bn0 = blockIdx.x * 128;

    const float* A;
    const float* bias;
    float* out;
    if (z < 4) {
        A = task_inputs;                       // shared experts see task 0 input
        bias = shared_b + z * NOUT;
        out = g_S + (size_t)z * MTOK * NOUT;
    } else {
        const int j = z - 4;
        A = task_inputs + (size_t)(j >> 1) * MTOK * KIN;
        bias = task_b + j * NOUT;
        out = g_T + (size_t)j * MTOK * NOUT;
    }
    const __nv_bfloat16* Wh = g_Wh + ((size_t)z * NOUT + bn0) * KIN;
    const __nv_bfloat16* Wl = g_Wl + ((size_t)z * NOUT + bn0) * KIN;

    if (tid < 128) sbias[tid] = bias[bn0 + tid];

    // warp tiling: 2 (m) x 4 (n); warp tile 64x32
    const int wm = warp & 1, wn = warp >> 1;
    const int m_base = wm * 64;
    const int n_base = wn * 32;

    // A staging: thread -> (row, half): 32 fp32 -> 4x16B hi + 4x16B lo
    const int a_row = tid >> 1, a_half = tid & 1;
    const float* a_src = A + (size_t)(bm0 + a_row) * KIN + a_half * 32;
    uint32_t a_off[4];
    #pragma unroll
    for (int c = 0; c < 4; c++)
        a_off[c] = SW((uint32_t)(a_row * 128 + a_half * 64 + c * 16));

    // B staging: 4 cp.async chunks per buffer per thread
    int b_n[4], b_seg[4];
    uint32_t b_off[4];
    #pragma unroll
    for (int c = 0; c < 4; c++) {
        int id = tid + 256 * c;
        b_n[c] = id >> 3;
        b_seg[c] = id & 7;
        b_off[c] = SW((uint32_t)(b_n[c] * 128 + b_seg[c] * 16));
    }

    // ldmatrix addresses (per ks added later)
    const int lr16 = lane & 15, lc16 = (lane >> 4) << 4;     // A x4
    const int lr8 = lane & 7, lb8 = ((lane >> 3) & 1) << 4;  // B x2

    float acc[4][4][4];
    #pragma unroll
    for (int mf = 0; mf < 4; mf++)
        #pragma unroll
        for (int nf = 0; nf < 4; nf++)
            #pragma unroll
            for (int r = 0; r < 4; r++) acc[mf][nf][r] = 0.f;

    // ---- prologue: full stage of kt=0 into buf 0 ----
    {
        char* bh = base + ST_BH;
        char* bl = base + ST_BL;
        #pragma unroll
        for (int c = 0; c < 4; c++) {
            const __nv_bfloat16* sh = Wh + (size_t)b_n[c] * KIN + b_seg[c] * 8;
            const __nv_bfloat16* sl = Wl + (size_t)b_n[c] * KIN + b_seg[c] * 8;
            cp_async16(smem_u32(bh + b_off[c]), sh);
            cp_async16(smem_u32(bl + b_off[c]), sl);
        }
        CP_COMMIT();
        float4 av[8];
        #pragma unroll
        for (int j = 0; j < 8; j++) av[j] = *(const float4*)(a_src + j * 4);
        char* ah = base + ST_AH;
        char* al = base + ST_AL;
        #pragma unroll
        for (int c = 0; c < 4; c++) {
            float f[8];
            f[0] = av[2 * c].x; f[1] = av[2 * c].y; f[2] = av[2 * c].z; f[3] = av[2 * c].w;
            f[4] = av[2 * c + 1].x; f[5] = av[2 * c + 1].y; f[6] = av[2 * c + 1].z; f[7] = av[2 * c + 1].w;
            uint4 h, l;
            cvt8(f, h, l);
            *(uint4*)(ah + a_off[c]) = h;
            *(uint4*)(al + a_off[c]) = l;
        }
        CP_WAIT0();
    }
    __syncthreads();

    #pragma unroll 1
    for (int kt = 0; kt < NKT; kt++) {
        const int buf = kt & 1;
        const int nbuf = buf ^ 1;
        const bool more = (kt + 1 < NKT);

        // issue next-stage loads first (overlap with compute)
        float4 av[8];
        if (more) {
            char* bh = base + nbuf * STAGE + ST_BH;
            char* bl = base + nbuf * STAGE + ST_BL;
            const int ko = (kt + 1) * 64;
            #pragma unroll
            for (int c = 0; c < 4; c++) {
                const __nv_bfloat16* sh = Wh + (size_t)b_n[c] * KIN + ko + b_seg[c] * 8;
                const __nv_bfloat16* sl = Wl + (size_t)b_n[c] * KIN + ko + b_seg[c] * 8;
                cp_async16(smem_u32(bh + b_off[c]), sh);
                cp_async16(smem_u32(bl + b_off[c]), sl);
            }
            CP_COMMIT();
            const float* asrc = a_src + ko;
            #pragma unroll
            for (int j = 0; j < 8; j++) av[j] = *(const float4*)(asrc + j * 4);
        }

        // compute on buf
        const uint32_t ahb = sb + buf * STAGE + ST_AH;
        const uint32_t alb = sb + buf * STAGE + ST_AL;
        const uint32_t bhb = sb + buf * STAGE + ST_BH;
        const uint32_t blb = sb + buf * STAGE + ST_BL;
        #pragma unroll
        for (int ks = 0; ks < 4; ks++) {
            uint32_t ah[4][4], al[4][4], bh[4][2], bl[4][2];
            #pragma unroll
            for (int mf = 0; mf < 4; mf++) {
                uint32_t off = SW((uint32_t)((m_base + mf * 16 + lr16) * 128 + ks * 32 + lc16));
                ldm_x4(ah[mf], ahb + off);
                ldm_x4(al[mf], alb + off);
            }
            #pragma unroll
            for (int nf = 0; nf < 4; nf++) {
                uint32_t off = SW((uint32_t)((n_base + nf * 8 + lr8) * 128 + ks * 32 + lb8));
                ldm_x2(bh[nf], bhb + off);
                ldm_x2(bl[nf], blb + off);
            }
            #pragma unroll
            for (int mf = 0; mf < 4; mf++)
                #pragma unroll
                for (int nf = 0; nf < 4; nf++) {
                    mma16816(acc[mf][nf], ah[mf], bh[nf]);
                    mma16816(acc[mf][nf], ah[mf], bl[nf]);
                    mma16816(acc[mf][nf], al[mf], bh[nf]);
                }
        }

        if (more) {
            char* ah = base + nbuf * STAGE + ST_AH;
            char* al = base + nbuf * STAGE + ST_AL;
            #pragma unroll
            for (int c = 0; c < 4; c++) {
                float f[8];
                f[0] = av[2 * c].x; f[1] = av[2 * c].y; f[2] = av[2 * c].z; f[3] = av[2 * c].w;
                f[4] = av[2 * c + 1].x; f[5] = av[2 * c + 1].y; f[6] = av[2 * c + 1].z; f[7] = av[2 * c + 1].w;
                uint4 h, l;
                cvt8(f, h, l);
                *(uint4*)(ah + a_off[c]) = h;
                *(uint4*)(al + a_off[c]) = l;
            }
            CP_WAIT0();
        }
        __syncthreads();
    }

    // ---- epilogue: bias + relu + store ----
    const int g = lane >> 2, i2 = (lane & 3) * 2;
    #pragma unroll
    for (int mf = 0; mf < 4; mf++) {
        const int r0 = bm0 + m_base + mf * 16 + g;
        #pragma unroll
        for (int nf = 0; nf < 4; nf++) {
            const int cl = n_base + nf * 8 + i2;      // col within tile
            const float b0 = sbias[cl], b1 = sbias[cl + 1];
            float2 v0, v1;
            v0.x = fmaxf(acc[mf][nf][0] + b0, 0.f);
            v0.y = fmaxf(acc[mf][nf][1] + b1, 0.f);
            v1.x = fmaxf(acc[mf][nf][2] + b0, 0.f);
            v1.y = fmaxf(acc[mf][nf][3] + b1, 0.f);
            *(float2*)(out + (size_t)r0 * NOUT + bn0 + cl) = v0;
            *(float2*)(out + (size_t)(r0 + 8) * NOUT + bn0 + cl) = v1;
        }
    }
}

// ---------------- gates -----------------------------------------------------
__global__ __launch_bounds__(256)
void gate_kernel(const float* __restrict__ task_inputs,
                 const float* __restrict__ gate_W,
                 const float* __restrict__ gate_b)
{
    __shared__ float Wg[KIN][9];
    const int t = blockIdx.y;
    for (int i = threadIdx.x; i < KIN * 6; i += 256)
        Wg[i / 6][i % 6] = gate_W[(size_t)t * KIN * 6 + i];
    __syncthreads();

    const int warp = threadIdx.x >> 5, lane = threadIdx.x & 31;
    const int b = blockIdx.x * 8 + warp;
    const float* x = task_inputs + ((size_t)t * MTOK + b) * KIN;

    float s[6] = {0.f, 0.f, 0.f, 0.f, 0.f, 0.f};
    #pragma unroll
    for (int i = 0; i < 8; i++) {
        const int k = i * 128 + lane * 4;
        float4 xv = *(const float4*)(x + k);
        float xa[4] = {xv.x, xv.y, xv.z, xv.w};
        #pragma unroll
        for (int j = 0; j < 4; j++)
            #pragma unroll
            for (int e = 0; e < 6; e++)
                s[e] = fmaf(xa[j], Wg[k + j][e], s[e]);
    }
    #pragma unroll
    for (int off = 16; off > 0; off >>= 1)
        #pragma unroll
        for (int e = 0; e < 6; e++)
            s[e] += __shfl_xor_sync(0xffffffffu, s[e], off);

    if (lane == 0) {
        float l[6], mx = -1e30f;
        #pragma unroll
        for (int e = 0; e < 6; e++) { l[e] = s[e] + gate_b[t * 6 + e]; mx = fmaxf(mx, l[e]); }
        float sum = 0.f;
        #pragma unroll
        for (int e = 0; e < 6; e++) { l[e] = __expf(l[e] - mx); sum += l[e]; }
        float inv = 1.f / sum;
        float* gp = g_G + ((size_t)t * MTOK + b) * 6;
        #pragma unroll
        for (int e = 0; e < 6; e++) gp[e] = l[e] * inv;
    }
}

// ---------------- combine ----------------------------------------------------
__global__ __launch_bounds__(256)
void combine_kernel(float* __restrict__ out)
{
    const size_t idx = (size_t)blockIdx.x * 256 + threadIdx.x;
    const size_t total = (size_t)NTASKS * MTOK * NOUT / 4;
    if (idx >= total) return;
    const int o4 = (int)(idx & (NOUT / 4 - 1));
    const size_t tb = idx >> 7;
    const int t = (int)(tb / MTOK);
    const int b = (int)(tb & (MTOK - 1));

    const float* g = g_G + tb * 6;
    float ge[6];
    #pragma unroll
    for (int e = 0; e < 6; e++) ge[e] = g[e];

    float4 r = make_float4(0.f, 0.f, 0.f, 0.f);
    #pragma unroll
    for (int e = 0; e < 4; e++) {
        const float4 s = *(const float4*)&g_S[(((size_t)e * MTOK) + b) * NOUT + o4 * 4];
        r.x = fmaf(ge[e], s.x, r.x);
        r.y = fmaf(ge[e], s.y, r.y);
        r.z = fmaf(ge[e], s.z, r.z);
        r.w = fmaf(ge[e], s.w, r.w);
    }
    #pragma unroll
    for (int e = 0; e < 2; e++) {
        const float4 s = *(const float4*)&g_T[(((size_t)(t * 2 + e) * MTOK) + b) * NOUT + o4 * 4];
        r.x = fmaf(ge[4 + e], s.x, r.x);
        r.y = fmaf(ge[4 + e], s.y, r.y);
        r.z = fmaf(ge[4 + e], s.z, r.z);
        r.w = fmaf(ge[4 + e], s.w, r.w);
    }
    *(float4*)(out + idx * 4) = r;
}

// ---------------- launch -----------------------------------------------------
extern "C" void kernel_launch(void* const* d_in, const int* in_sizes, int n_in,
                              void* d_out, int out_size)
{
    const float* task_inputs = (const float*)d_in[0];
    const float* shared_W    = (const float*)d_in[1];
    const float* shared_b    = (const float*)d_in[2];
    const float* task_W      = (const float*)d_in[3];
    const float* task_b      = (const float*)d_in[4];
    const float* gate_W      = (const float*)d_in[5];
    const float* gate_b      = (const float*)d_in[6];
    float* out = (float*)d_out;

    cudaFuncSetAttribute(gemm_mma_kernel,
                         cudaFuncAttributeMaxDynamicSharedMemorySize, SMEM_BYTES);

    // 1) W transpose + bf16 hi/lo split
    wprep_kernel<<<dim3(KIN / 32, NOUT / 32, NEXP), 256>>>(shared_W, task_W);

    // 2) gates
    gate_kernel<<<dim3(MTOK / 8, NTASKS), 256>>>(task_inputs, gate_W, gate_b);

    // 3) 10 expert GEMMs, bf16x3 split on HMMA (mma.sync)
    gemm_mma_kernel<<<dim3(NOUT / 128, MTOK / 128, NEXP), 256, SMEM_BYTES>>>(
        task_inputs, shared_b, task_b);

    // 4) gated combine
    const size_t total4 = (size_t)NTASKS * MTOK * NOUT / 4;
    combine_kernel<<<(unsigned)((total4 + 255) / 256), 256>>>(out);
}

// round 5
// speedup vs baseline: 1.7693x; 1.0541x over previous
#include <cuda_runtime.h>
#include <cuda_bf16.h>
#include <cstdint>
#include <math.h>

#define MTOK 16384
#define NOUT 512
#define KIN  1024
#define NTASKS 3
#define NEXP 10

// ---------------- scratch (device globals; no allocations allowed) ----------
__device__ float g_S[(size_t)4 * MTOK * NOUT];            // shared-expert outs
__device__ float g_T[(size_t)6 * MTOK * NOUT];            // task-expert outs
__device__ float g_G[(size_t)NTASKS * MTOK * 6];          // softmaxed gates
__device__ __nv_bfloat16 g_Wh[(size_t)NEXP * NOUT * KIN]; // W^T hi, [e][n][k]
__device__ __nv_bfloat16 g_Wl[(size_t)NEXP * NOUT * KIN]; // W^T lo
__device__ __nv_bfloat16 g_Ah[(size_t)NTASKS * MTOK * KIN]; // A hi, [t][m][k]
__device__ __nv_bfloat16 g_Al[(size_t)NTASKS * MTOK * KIN]; // A lo

// ---------------- helpers ----------------------------------------------------
__device__ __forceinline__ uint32_t smem_u32(const void* p) {
    uint32_t a;
    asm("{ .reg .u64 t; cvta.to.shared.u64 t, %1; cvt.u32.u64 %0, t; }"
        : "=r"(a) : "l"(p));
    return a;
}
// SW64 swizzle for 64-byte rows (conflict-free ldmatrix, verified bank walk)
__device__ __forceinline__ uint32_t SW64(uint32_t o) { return o ^ ((o >> 3) & 0x30); }

__device__ __forceinline__ void cp_async16(uint32_t dst, const void* src) {
    asm volatile("cp.async.cg.shared.global [%0], [%1], 16;"
                 :: "r"(dst), "l"(src) : "memory");
}
#define CP_COMMIT() asm volatile("cp.async.commit_group;" ::: "memory")
#define CP_WAIT1()  asm volatile("cp.async.wait_group 1;" ::: "memory")

__device__ __forceinline__ void ldm_x4(uint32_t* r, uint32_t addr) {
    asm volatile("ldmatrix.sync.aligned.m8n8.x4.shared.b16 {%0,%1,%2,%3}, [%4];"
                 : "=r"(r[0]), "=r"(r[1]), "=r"(r[2]), "=r"(r[3]) : "r"(addr));
}
__device__ __forceinline__ void mma16816(float* c, const uint32_t* a, const uint32_t* b) {
    asm volatile("mma.sync.aligned.m16n8k16.row.col.f32.bf16.bf16.f32 "
                 "{%0,%1,%2,%3}, {%4,%5,%6,%7}, {%8,%9}, {%0,%1,%2,%3};"
                 : "+f"(c[0]), "+f"(c[1]), "+f"(c[2]), "+f"(c[3])
                 : "r"(a[0]), "r"(a[1]), "r"(a[2]), "r"(a[3]), "r"(b[0]), "r"(b[1]));
}

__device__ __forceinline__ void cvt8(const float* f, uint4& h, uint4& l) {
    uint32_t hh[4], ll[4];
    #pragma unroll
    for (int i = 0; i < 4; i++) {
        float a = f[2 * i], b = f[2 * i + 1];
        __nv_bfloat16 ah = __float2bfloat16(a);
        __nv_bfloat16 bh = __float2bfloat16(b);
        __nv_bfloat16 al = __float2bfloat16(a - __bfloat162float(ah));
        __nv_bfloat16 bl = __float2bfloat16(b - __bfloat162float(bh));
        __nv_bfloat162 hv; hv.x = ah; hv.y = bh;
        __nv_bfloat162 lv; lv.x = al; lv.y = bl;
        hh[i] = *reinterpret_cast<uint32_t*>(&hv);
        ll[i] = *reinterpret_cast<uint32_t*>(&lv);
    }
    h = make_uint4(hh[0], hh[1], hh[2], hh[3]);
    l = make_uint4(ll[0], ll[1], ll[2], ll[3]);
}

// ---------------- A prep: fp32 -> bf16 hi/lo -------------------------------
__global__ __launch_bounds__(256)
void asplit_kernel(const float* __restrict__ task_inputs)
{
    const size_t i = ((size_t)blockIdx.x * 256 + threadIdx.x) * 8;
    float f[8];
    float4 v0 = *(const float4*)(task_inputs + i);
    float4 v1 = *(const float4*)(task_inputs + i + 4);
    f[0] = v0.x; f[1] = v0.y; f[2] = v0.z; f[3] = v0.w;
    f[4] = v1.x; f[5] = v1.y; f[6] = v1.z; f[7] = v1.w;
    uint4 h, l;
    cvt8(f, h, l);
    *(uint4*)(g_Ah + i) = h;
    *(uint4*)(g_Al + i) = l;
}

// ---------------- W prep: transpose + bf16 hi/lo split ----------------------
__global__ __launch_bounds__(256)
void wprep_kernel(const float* __restrict__ shared_W, const float* __restrict__ task_W)
{
    __shared__ float tile[32][33];
    const int e = blockIdx.z;
    const float* W = (e < 4) ? shared_W + (size_t)e * KIN * NOUT
                             : task_W + (size_t)(e - 4) * KIN * NOUT;
    const int k0 = blockIdx.x * 32, n0 = blockIdx.y * 32;
    const int tx = threadIdx.x & 31, ty = threadIdx.x >> 5;

    #pragma unroll
    for (int i = 0; i < 4; i++)
        tile[ty + i * 8][tx] = W[(size_t)(k0 + ty + i * 8) * NOUT + n0 + tx];
    __syncthreads();
    #pragma unroll
    for (int i = 0; i < 4; i++) {
        float v = tile[tx][ty + i * 8];
        __nv_bfloat16 hi = __float2bfloat16(v);
        __nv_bfloat16 lo = __float2bfloat16(v - __bfloat162float(hi));
        size_t idx = ((size_t)e * NOUT + (n0 + ty + i * 8)) * KIN + k0 + tx;
        g_Wh[idx] = hi;
        g_Wl[idx] = lo;
    }
}

// ---------------- HMMA GEMM: 128x256 CTA tile, K chunks of 32, 3 stages -----
#define BM 128
#define BN 256
#define BK 32
#define NKT (KIN / BK)     // 32
#define ST_AH 0
#define ST_AL 8192
#define ST_BH 16384
#define ST_BL 32768
#define STAGE_SZ 49152
#define SMEM_BYTES (3 * STAGE_SZ + 1024)

__global__ __launch_bounds__(256, 1)
void gemm_mma_kernel(const float* __restrict__ shared_b,
                     const float* __restrict__ task_b)
{
    extern __shared__ char dsm[];
    __shared__ float sbias[BN];

    const uint32_t raw = smem_u32(dsm);
    const uint32_t sb = (raw + 1023u) & ~1023u;

    const int tid = threadIdx.x;
    const int warp = tid >> 5;
    const int lane = tid & 31;

    const int z = blockIdx.z;
    const int bm0 = blockIdx.y * BM;
    const int bn0 = blockIdx.x * BN;

    const __nv_bfloat16* Ah;
    const float* bias;
    float* out;
    if (z < 4) {
        Ah = g_Ah;                                   // shared experts: task 0
        bias = shared_b + z * NOUT;
        out = g_S + (size_t)z * MTOK * NOUT;
    } else {
        const int j = z - 4;
        Ah = g_Ah + (size_t)(j >> 1) * MTOK * KIN;
        bias = task_b + j * NOUT;
        out = g_T + (size_t)j * MTOK * NOUT;
    }
    const __nv_bfloat16* Al = Ah + ((size_t)NTASKS * MTOK * KIN -
                                    (Ah - g_Ah) + (g_Al - g_Al));  // same offset in g_Al
    Al = g_Al + (Ah - g_Ah);
    const __nv_bfloat16* Wh = g_Wh + ((size_t)z * NOUT + bn0) * KIN;
    const __nv_bfloat16* Wl = g_Wl + ((size_t)z * NOUT + bn0) * KIN;

    sbias[tid] = bias[bn0 + tid];

    // ---- staging assignments ----
    // A: 128 rows x 32 k = 512 x 16B (hi) ; thread -> row=tid>>1, segs (tid&1)*2+{0,1}
    const int a_row = tid >> 1;
    const int a_seg0 = (tid & 1) * 2;
    uint32_t a_off[2];
    #pragma unroll
    for (int c = 0; c < 2; c++)
        a_off[c] = SW64((uint32_t)(a_row * 64 + (a_seg0 + c) * 16));
    const __nv_bfloat16* a_hsrc = Ah + (size_t)(bm0 + a_row) * KIN + a_seg0 * 8;
    const __nv_bfloat16* a_lsrc = Al + (size_t)(bm0 + a_row) * KIN + a_seg0 * 8;

    // B: 256 rows x 32 k = 1024 x 16B (hi); thread -> 4 chunks
    int b_row[4];
    uint32_t b_off[4];
    const int b_seg = tid & 3;
    #pragma unroll
    for (int c = 0; c < 4; c++) {
        b_row[c] = (tid >> 2) + c * 64;
        b_off[c] = SW64((uint32_t)(b_row[c] * 64 + b_seg * 16));
    }
    const __nv_bfloat16* b_hsrc[4];
    const __nv_bfloat16* b_lsrc[4];
    #pragma unroll
    for (int c = 0; c < 4; c++) {
        b_hsrc[c] = Wh + (size_t)b_row[c] * KIN + b_seg * 8;
        b_lsrc[c] = Wl + (size_t)b_row[c] * KIN + b_seg * 8;
    }

    // warp tiling: 2(M) x 4(N); warp tile 64x64
    const int wm = warp & 1, wn = warp >> 1;
    const int m_base = wm * 64;
    const int n_base = wn * 64;
    const int lr16 = lane & 15, lc16 = (lane >> 4) << 4;

    float acc[4][8][4];
    #pragma unroll
    for (int mf = 0; mf < 4; mf++)
        #pragma unroll
        for (int nf = 0; nf < 8; nf++)
            #pragma unroll
            for (int r = 0; r < 4; r++) acc[mf][nf][r] = 0.f;

    auto issue = [&](int kt, int s) {
        const uint32_t sa = sb + s * STAGE_SZ;
        const int ko = kt * BK;
        #pragma unroll
        for (int c = 0; c < 2; c++) {
            cp_async16(sa + ST_AH + a_off[c], a_hsrc + ko + c * 8);
            cp_async16(sa + ST_AL + a_off[c], a_lsrc + ko + c * 8);
        }
        #pragma unroll
        for (int c = 0; c < 4; c++) {
            cp_async16(sa + ST_BH + b_off[c], b_hsrc[c] + ko);
            cp_async16(sa + ST_BL + b_off[c], b_lsrc[c] + ko);
        }
    };

    // prologue: stages for kt=0,1
    issue(0, 0); CP_COMMIT();
    issue(1, 1); CP_COMMIT();

    #pragma unroll 1
    for (int kt = 0; kt < NKT; kt++) {
        CP_WAIT1();
        __syncthreads();

        if (kt + 2 < NKT) issue(kt + 2, (kt + 2) % 3);
        CP_COMMIT();   // always commit (possibly empty) to keep group count fixed

        const uint32_t ab = sb + (kt % 3) * STAGE_SZ;
        #pragma unroll
        for (int ks = 0; ks < 2; ks++) {
            // B frags: 4 ldm_x4 pairs (hi) + 4 (lo)
            uint32_t bh[8][2], bl[8][2];
            #pragma unroll
            for (int pr = 0; pr < 4; pr++) {
                uint32_t off = SW64((uint32_t)((n_base + pr * 16 + lr16) * 64 + ks * 32 + lc16));
                uint32_t r[4];
                ldm_x4(r, ab + ST_BH + off);
                bh[2 * pr][0] = r[0]; bh[2 * pr + 1][0] = r[1];
                bh[2 * pr][1] = r[2]; bh[2 * pr + 1][1] = r[3];
                ldm_x4(r, ab + ST_BL + off);
                bl[2 * pr][0] = r[0]; bl[2 * pr + 1][0] = r[1];
                bl[2 * pr][1] = r[2]; bl[2 * pr + 1][1] = r[3];
            }
            #pragma unroll
            for (int mf = 0; mf < 4; mf++) {
                uint32_t off = SW64((uint32_t)((m_base + mf * 16 + lr16) * 64 + ks * 32 + lc16));
                uint32_t ah[4], al[4];
                ldm_x4(ah, ab + ST_AH + off);
                ldm_x4(al, ab + ST_AL + off);
                #pragma unroll
                for (int nf = 0; nf < 8; nf++) {
                    mma16816(acc[mf][nf], ah, bh[nf]);
                    mma16816(acc[mf][nf], ah, bl[nf]);
                    mma16816(acc[mf][nf], al, bh[nf]);
                }
            }
        }
    }

    // ---- epilogue: bias + relu + store ----
    const int g = lane >> 2, i2 = (lane & 3) * 2;
    #pragma unroll
    for (int mf = 0; mf < 4; mf++) {
        const int r0 = bm0 + m_base + mf * 16 + g;
        #pragma unroll
        for (int nf = 0; nf < 8; nf++) {
            const int cl = n_base + nf * 8 + i2;
            const float b0 = sbias[cl], b1 = sbias[cl + 1];
            float2 v0, v1;
            v0.x = fmaxf(acc[mf][nf][0] + b0, 0.f);
            v0.y = fmaxf(acc[mf][nf][1] + b1, 0.f);
            v1.x = fmaxf(acc[mf][nf][2] + b0, 0.f);
            v1.y = fmaxf(acc[mf][nf][3] + b1, 0.f);
            *(float2*)(out + (size_t)r0 * NOUT + bn0 + cl) = v0;
            *(float2*)(out + (size_t)(r0 + 8) * NOUT + bn0 + cl) = v1;
        }
    }
}

// ---------------- gates -----------------------------------------------------
__global__ __launch_bounds__(256)
void gate_kernel(const float* __restrict__ task_inputs,
                 const float* __restrict__ gate_W,
                 const float* __restrict__ gate_b)
{
    __shared__ float Wg[KIN][9];
    const int t = blockIdx.y;
    for (int i = threadIdx.x; i < KIN * 6; i += 256)
        Wg[i / 6][i % 6] = gate_W[(size_t)t * KIN * 6 + i];
    __syncthreads();

    const int warp = threadIdx.x >> 5, lane = threadIdx.x & 31;
    const int b = blockIdx.x * 8 + warp;
    const float* x = task_inputs + ((size_t)t * MTOK + b) * KIN;

    float s[6] = {0.f, 0.f, 0.f, 0.f, 0.f, 0.f};
    #pragma unroll
    for (int i = 0; i < 8; i++) {
        const int k = i * 128 + lane * 4;
        float4 xv = *(const float4*)(x + k);
        float xa[4] = {xv.x, xv.y, xv.z, xv.w};
        #pragma unroll
        for (int j = 0; j < 4; j++)
            #pragma unroll
            for (int e = 0; e < 6; e++)
                s[e] = fmaf(xa[j], Wg[k + j][e], s[e]);
    }
    #pragma unroll
    for (int off = 16; off > 0; off >>= 1)
        #pragma unroll
        for (int e = 0; e < 6; e++)
            s[e] += __shfl_xor_sync(0xffffffffu, s[e], off);

    if (lane == 0) {
        float l[6], mx = -1e30f;
        #pragma unroll
        for (int e = 0; e < 6; e++) { l[e] = s[e] + gate_b[t * 6 + e]; mx = fmaxf(mx, l[e]); }
        float sum = 0.f;
        #pragma unroll
        for (int e = 0; e < 6; e++) { l[e] = __expf(l[e] - mx); sum += l[e]; }
        float inv = 1.f / sum;
        float* gp = g_G + ((size_t)t * MTOK + b) * 6;
        #pragma unroll
        for (int e = 0; e < 6; e++) gp[e] = l[e] * inv;
    }
}

// ---------------- combine ----------------------------------------------------
__global__ __launch_bounds__(256)
void combine_kernel(float* __restrict__ out)
{
    const size_t idx = (size_t)blockIdx.x * 256 + threadIdx.x;
    const size_t total = (size_t)NTASKS * MTOK * NOUT / 4;
    if (idx >= total) return;
    const int o4 = (int)(idx & (NOUT / 4 - 1));
    const size_t tb = idx >> 7;
    const int t = (int)(tb / MTOK);
    const int b = (int)(tb & (MTOK - 1));

    const float* g = g_G + tb * 6;
    float ge[6];
    #pragma unroll
    for (int e = 0; e < 6; e++) ge[e] = g[e];

    float4 r = make_float4(0.f, 0.f, 0.f, 0.f);
    #pragma unroll
    for (int e = 0; e < 4; e++) {
        const float4 s = *(const float4*)&g_S[(((size_t)e * MTOK) + b) * NOUT + o4 * 4];
        r.x = fmaf(ge[e], s.x, r.x);
        r.y = fmaf(ge[e], s.y, r.y);
        r.z = fmaf(ge[e], s.z, r.z);
        r.w = fmaf(ge[e], s.w, r.w);
    }
    #pragma unroll
    for (int e = 0; e < 2; e++) {
        const float4 s = *(const float4*)&g_T[(((size_t)(t * 2 + e) * MTOK) + b) * NOUT + o4 * 4];
        r.x = fmaf(ge[4 + e], s.x, r.x);
        r.y = fmaf(ge[4 + e], s.y, r.y);
        r.z = fmaf(ge[4 + e], s.z, r.z);
        r.w = fmaf(ge[4 + e], s.w, r.w);
    }
    *(float4*)(out + idx * 4) = r;
}

// ---------------- launch -----------------------------------------------------
extern "C" void kernel_launch(void* const* d_in, const int* in_sizes, int n_in,
                              void* d_out, int out_size)
{
    const float* task_inputs = (const float*)d_in[0];
    const float* shared_W    = (const float*)d_in[1];
    const float* shared_b    = (const float*)d_in[2];
    const float* task_W      = (const float*)d_in[3];
    const float* task_b      = (const float*)d_in[4];
    const float* gate_W      = (const float*)d_in[5];
    const float* gate_b      = (const float*)d_in[6];
    float* out = (float*)d_out;

    cudaFuncSetAttribute(gemm_mma_kernel,
                         cudaFuncAttributeMaxDynamicSharedMemorySize, SMEM_BYTES);

    // 1) A split (fp32 -> bf16 hi/lo)
    const size_t atot = (size_t)NTASKS * MTOK * KIN;            // 50331648
    asplit_kernel<<<(unsigned)(atot / 8 / 256), 256>>>(task_inputs);

    // 2) W transpose + bf16 hi/lo split
    wprep_kernel<<<dim3(KIN / 32, NOUT / 32, NEXP), 256>>>(shared_W, task_W);

    // 3) gates
    gate_kernel<<<dim3(MTOK / 8, NTASKS), 256>>>(task_inputs, gate_W, gate_b);

    // 4) 10 expert GEMMs, bf16x3 split on HMMA, pure cp.async pipeline
    gemm_mma_kernel<<<dim3(NOUT / BN, MTOK / BM, NEXP), 256, SMEM_BYTES>>>(
        shared_b, task_b);

    // 5) gated combine
    const size_t total4 = (size_t)NTASKS * MTOK * NOUT / 4;
    combine_kernel<<<(unsigned)((total4 + 255) / 256), 256>>>(out);
}

// round 6
// speedup vs baseline: 1.9703x; 1.1136x over previous
#include <cuda_runtime.h>
#include <cuda_bf16.h>
#include <cstdint>
#include <math.h>

#define MTOK 16384
#define NOUT 512
#define KIN  1024
#define NTASKS 3
#define NEXP 10

// ---------------- scratch (device globals; no allocations allowed) ----------
__device__ float g_S[(size_t)4 * MTOK * NOUT];            // shared-expert outs
__device__ float g_T[(size_t)6 * MTOK * NOUT];            // task-expert outs
__device__ float g_G[(size_t)NTASKS * MTOK * 6];          // softmaxed gates
__device__ __nv_bfloat16 g_Wh[(size_t)NEXP * NOUT * KIN]; // W^T hi, [e][n][k]
__device__ __nv_bfloat16 g_Wl[(size_t)NEXP * NOUT * KIN]; // W^T lo
__device__ __nv_bfloat16 g_Ah[(size_t)NTASKS * MTOK * KIN]; // A hi, [t][m][k]
__device__ __nv_bfloat16 g_Al[(size_t)NTASKS * MTOK * KIN]; // A lo

// ---------------- helpers ----------------------------------------------------
__device__ __forceinline__ uint32_t smem_u32(const void* p) {
    uint32_t a;
    asm("{ .reg .u64 t; cvta.to.shared.u64 t, %1; cvt.u32.u64 %0, t; }"
        : "=r"(a) : "l"(p));
    return a;
}
__device__ __forceinline__ uint32_t SW64(uint32_t o) { return o ^ ((o >> 3) & 0x30); }

__device__ __forceinline__ void cp_async16(uint32_t dst, const void* src) {
    asm volatile("cp.async.cg.shared.global [%0], [%1], 16;"
                 :: "r"(dst), "l"(src) : "memory");
}
#define CP_COMMIT() asm volatile("cp.async.commit_group;" ::: "memory")
#define CP_WAIT1()  asm volatile("cp.async.wait_group 1;" ::: "memory")

__device__ __forceinline__ void ldm_x4(uint32_t* r, uint32_t addr) {
    asm volatile("ldmatrix.sync.aligned.m8n8.x4.shared.b16 {%0,%1,%2,%3}, [%4];"
                 : "=r"(r[0]), "=r"(r[1]), "=r"(r[2]), "=r"(r[3]) : "r"(addr));
}
__device__ __forceinline__ void mma16816(float* c, const uint32_t* a, const uint32_t* b) {
    asm volatile("mma.sync.aligned.m16n8k16.row.col.f32.bf16.bf16.f32 "
                 "{%0,%1,%2,%3}, {%4,%5,%6,%7}, {%8,%9}, {%0,%1,%2,%3};"
                 : "+f"(c[0]), "+f"(c[1]), "+f"(c[2]), "+f"(c[3])
                 : "r"(a[0]), "r"(a[1]), "r"(a[2]), "r"(a[3]), "r"(b[0]), "r"(b[1]));
}

__device__ __forceinline__ void cvt8(const float* f, uint4& h, uint4& l) {
    uint32_t hh[4], ll[4];
    #pragma unroll
    for (int i = 0; i < 4; i++) {
        float a = f[2 * i], b = f[2 * i + 1];
        __nv_bfloat16 ah = __float2bfloat16(a);
        __nv_bfloat16 bh = __float2bfloat16(b);
        __nv_bfloat16 al = __float2bfloat16(a - __bfloat162float(ah));
        __nv_bfloat16 bl = __float2bfloat16(b - __bfloat162float(bh));
        __nv_bfloat162 hv; hv.x = ah; hv.y = bh;
        __nv_bfloat162 lv; lv.x = al; lv.y = bl;
        hh[i] = *reinterpret_cast<uint32_t*>(&hv);
        ll[i] = *reinterpret_cast<uint32_t*>(&lv);
    }
    h = make_uint4(hh[0], hh[1], hh[2], hh[3]);
    l = make_uint4(ll[0], ll[1], ll[2], ll[3]);
}

// ---------------- A prep: fp32 -> bf16 hi/lo -------------------------------
__global__ __launch_bounds__(256)
void asplit_kernel(const float* __restrict__ task_inputs)
{
    const size_t i = ((size_t)blockIdx.x * 256 + threadIdx.x) * 8;
    float f[8];
    float4 v0 = *(const float4*)(task_inputs + i);
    float4 v1 = *(const float4*)(task_inputs + i + 4);
    f[0] = v0.x; f[1] = v0.y; f[2] = v0.z; f[3] = v0.w;
    f[4] = v1.x; f[5] = v1.y; f[6] = v1.z; f[7] = v1.w;
    uint4 h, l;
    cvt8(f, h, l);
    *(uint4*)(g_Ah + i) = h;
    *(uint4*)(g_Al + i) = l;
}

// ---------------- W prep: transpose + bf16 hi/lo split ----------------------
__global__ __launch_bounds__(256)
void wprep_kernel(const float* __restrict__ shared_W, const float* __restrict__ task_W)
{
    __shared__ float tile[32][33];
    const int e = blockIdx.z;
    const float* W = (e < 4) ? shared_W + (size_t)e * KIN * NOUT
                             : task_W + (size_t)(e - 4) * KIN * NOUT;
    const int k0 = blockIdx.x * 32, n0 = blockIdx.y * 32;
    const int tx = threadIdx.x & 31, ty = threadIdx.x >> 5;

    #pragma unroll
    for (int i = 0; i < 4; i++)
        tile[ty + i * 8][tx] = W[(size_t)(k0 + ty + i * 8) * NOUT + n0 + tx];
    __syncthreads();
    #pragma unroll
    for (int i = 0; i < 4; i++) {
        float v = tile[tx][ty + i * 8];
        __nv_bfloat16 hi = __float2bfloat16(v);
        __nv_bfloat16 lo = __float2bfloat16(v - __bfloat162float(hi));
        size_t idx = ((size_t)e * NOUT + (n0 + ty + i * 8)) * KIN + k0 + tx;
        g_Wh[idx] = hi;
        g_Wl[idx] = lo;
    }
}

// ---------------- HMMA GEMM: 128x256 CTA, 16 warps, K chunks of 32, 3 stages
#define BM 128
#define BN 256
#define BK 32
#define NKT (KIN / BK)     // 32
#define ST_AH 0
#define ST_AL 8192
#define ST_BH 16384
#define ST_BL 32768
#define STAGE_SZ 49152
#define SMEM_BYTES (3 * STAGE_SZ + 1024)

__global__ __launch_bounds__(512, 1)
void gemm_mma_kernel(const float* __restrict__ shared_b,
                     const float* __restrict__ task_b)
{
    extern __shared__ char dsm[];
    __shared__ float sbias[BN];

    const uint32_t raw = smem_u32(dsm);
    const uint32_t sb = (raw + 1023u) & ~1023u;

    const int tid = threadIdx.x;
    const int warp = tid >> 5;
    const int lane = tid & 31;

    const int z = blockIdx.z;
    const int bm0 = blockIdx.y * BM;
    const int bn0 = blockIdx.x * BN;

    size_t a_base;
    const float* bias;
    float* out;
    if (z < 4) {
        a_base = 0;                                  // shared experts: task 0
        bias = shared_b + z * NOUT;
        out = g_S + (size_t)z * MTOK * NOUT;
    } else {
        const int j = z - 4;
        a_base = (size_t)(j >> 1) * MTOK * KIN;
        bias = task_b + j * NOUT;
        out = g_T + (size_t)j * MTOK * NOUT;
    }
    const __nv_bfloat16* Ah = g_Ah + a_base;
    const __nv_bfloat16* Al = g_Al + a_base;
    const __nv_bfloat16* Wh = g_Wh + ((size_t)z * NOUT + bn0) * KIN;
    const __nv_bfloat16* Wl = g_Wl + ((size_t)z * NOUT + bn0) * KIN;

    if (tid < BN) sbias[tid] = bias[bn0 + tid];

    // ---- staging assignments (512 threads) ----
    // A: 128 rows x 32k -> 512 x 16B chunks, 1 per thread
    const int a_row = tid >> 2;
    const int a_seg = tid & 3;
    const uint32_t a_off = SW64((uint32_t)(a_row * 64 + a_seg * 16));
    const __nv_bfloat16* a_hsrc = Ah + (size_t)(bm0 + a_row) * KIN + a_seg * 8;
    const __nv_bfloat16* a_lsrc = Al + (size_t)(bm0 + a_row) * KIN + a_seg * 8;

    // B: 256 rows x 32k -> 1024 x 16B chunks, 2 per thread
    const int b_seg = tid & 3;
    int b_row[2];
    uint32_t b_off[2];
    const __nv_bfloat16* b_hsrc[2];
    const __nv_bfloat16* b_lsrc[2];
    #pragma unroll
    for (int c = 0; c < 2; c++) {
        b_row[c] = (tid >> 2) + c * 128;
        b_off[c] = SW64((uint32_t)(b_row[c] * 64 + b_seg * 16));
        b_hsrc[c] = Wh + (size_t)b_row[c] * KIN + b_seg * 8;
        b_lsrc[c] = Wl + (size_t)b_row[c] * KIN + b_seg * 8;
    }

    // warp tiling: 4(M) x 4(N); warp tile 32x64
    const int wm = warp & 3, wn = warp >> 2;
    const int m_base = wm * 32;
    const int n_base = wn * 64;
    const int lr16 = lane & 15, lc16 = (lane >> 4) << 4;

    float acc[2][8][4];
    #pragma unroll
    for (int mf = 0; mf < 2; mf++)
        #pragma unroll
        for (int nf = 0; nf < 8; nf++)
            #pragma unroll
            for (int r = 0; r < 4; r++) acc[mf][nf][r] = 0.f;

    auto issue = [&](int kt, int s) {
        const uint32_t sa = sb + s * STAGE_SZ;
        const int ko = kt * BK;
        cp_async16(sa + ST_AH + a_off, a_hsrc + ko);
        cp_async16(sa + ST_AL + a_off, a_lsrc + ko);
        #pragma unroll
        for (int c = 0; c < 2; c++) {
            cp_async16(sa + ST_BH + b_off[c], b_hsrc[c] + ko);
            cp_async16(sa + ST_BL + b_off[c], b_lsrc[c] + ko);
        }
    };

    issue(0, 0); CP_COMMIT();
    issue(1, 1); CP_COMMIT();

    #pragma unroll 1
    for (int kt = 0; kt < NKT; kt++) {
        CP_WAIT1();
        __syncthreads();

        if (kt + 2 < NKT) issue(kt + 2, (kt + 2) % 3);
        CP_COMMIT();

        const uint32_t ab = sb + (kt % 3) * STAGE_SZ;
        #pragma unroll
        for (int ks = 0; ks < 2; ks++) {
            // load all fragments for this ks
            uint32_t ah[2][4], al[2][4];
            uint32_t bh[8][2], bl[8][2];
            #pragma unroll
            for (int mf = 0; mf < 2; mf++) {
                uint32_t off = SW64((uint32_t)((m_base + mf * 16 + lr16) * 64 + ks * 32 + lc16));
                ldm_x4(ah[mf], ab + ST_AH + off);
                ldm_x4(al[mf], ab + ST_AL + off);
            }
            #pragma unroll
            for (int pr = 0; pr < 4; pr++) {
                uint32_t off = SW64((uint32_t)((n_base + pr * 16 + lr16) * 64 + ks * 32 + lc16));
                uint32_t r[4];
                ldm_x4(r, ab + ST_BH + off);
                bh[2 * pr][0] = r[0]; bh[2 * pr + 1][0] = r[1];
                bh[2 * pr][1] = r[2]; bh[2 * pr + 1][1] = r[3];
                ldm_x4(r, ab + ST_BL + off);
                bl[2 * pr][0] = r[0]; bl[2 * pr + 1][0] = r[1];
                bl[2 * pr][1] = r[2]; bl[2 * pr + 1][1] = r[3];
            }
            // term-major: no two consecutive MMAs share an accumulator
            #pragma unroll
            for (int mf = 0; mf < 2; mf++)
                #pragma unroll
                for (int nf = 0; nf < 8; nf++)
                    mma16816(acc[mf][nf], ah[mf], bh[nf]);
            #pragma unroll
            for (int mf = 0; mf < 2; mf++)
                #pragma unroll
                for (int nf = 0; nf < 8; nf++)
                    mma16816(acc[mf][nf], ah[mf], bl[nf]);
            #pragma unroll
            for (int mf = 0; mf < 2; mf++)
                #pragma unroll
                for (int nf = 0; nf < 8; nf++)
                    mma16816(acc[mf][nf], al[mf], bh[nf]);
        }
    }

    // ---- epilogue: bias + relu + store ----
    const int g = lane >> 2, i2 = (lane & 3) * 2;
    #pragma unroll
    for (int mf = 0; mf < 2; mf++) {
        const int r0 = bm0 + m_base + mf * 16 + g;
        #pragma unroll
        for (int nf = 0; nf < 8; nf++) {
            const int cl = n_base + nf * 8 + i2;
            const float b0 = sbias[cl], b1 = sbias[cl + 1];
            float2 v0, v1;
            v0.x = fmaxf(acc[mf][nf][0] + b0, 0.f);
            v0.y = fmaxf(acc[mf][nf][1] + b1, 0.f);
            v1.x = fmaxf(acc[mf][nf][2] + b0, 0.f);
            v1.y = fmaxf(acc[mf][nf][3] + b1, 0.f);
            *(float2*)(out + (size_t)r0 * NOUT + bn0 + cl) = v0;
            *(float2*)(out + (size_t)(r0 + 8) * NOUT + bn0 + cl) = v1;
        }
    }
}

// ---------------- gates -----------------------------------------------------
__global__ __launch_bounds__(256)
void gate_kernel(const float* __restrict__ task_inputs,
                 const float* __restrict__ gate_W,
                 const float* __restrict__ gate_b)
{
    __shared__ float Wg[KIN][9];
    const int t = blockIdx.y;
    for (int i = threadIdx.x; i < KIN * 6; i += 256)
        Wg[i / 6][i % 6] = gate_W[(size_t)t * KIN * 6 + i];
    __syncthreads();

    const int warp = threadIdx.x >> 5, lane = threadIdx.x & 31;
    const int b = blockIdx.x * 8 + warp;
    const float* x = task_inputs + ((size_t)t * MTOK + b) * KIN;

    float s[6] = {0.f, 0.f, 0.f, 0.f, 0.f, 0.f};
    #pragma unroll
    for (int i = 0; i < 8; i++) {
        const int k = i * 128 + lane * 4;
        float4 xv = *(const float4*)(x + k);
        float xa[4] = {xv.x, xv.y, xv.z, xv.w};
        #pragma unroll
        for (int j = 0; j < 4; j++)
            #pragma unroll
            for (int e = 0; e < 6; e++)
                s[e] = fmaf(xa[j], Wg[k + j][e], s[e]);
    }
    #pragma unroll
    for (int off = 16; off > 0; off >>= 1)
        #pragma unroll
        for (int e = 0; e < 6; e++)
            s[e] += __shfl_xor_sync(0xffffffffu, s[e], off);

    if (lane == 0) {
        float l[6], mx = -1e30f;
        #pragma unroll
        for (int e = 0; e < 6; e++) { l[e] = s[e] + gate_b[t * 6 + e]; mx = fmaxf(mx, l[e]); }
        float sum = 0.f;
        #pragma unroll
        for (int e = 0; e < 6; e++) { l[e] = __expf(l[e] - mx); sum += l[e]; }
        float inv = 1.f / sum;
        float* gp = g_G + ((size_t)t * MTOK + b) * 6;
        #pragma unroll
        for (int e = 0; e < 6; e++) gp[e] = l[e] * inv;
    }
}

// ---------------- combine ----------------------------------------------------
__global__ __launch_bounds__(256)
void combine_kernel(float* __restrict__ out)
{
    const size_t idx = (size_t)blockIdx.x * 256 + threadIdx.x;
    const size_t total = (size_t)NTASKS * MTOK * NOUT / 4;
    if (idx >= total) return;
    const int o4 = (int)(idx & (NOUT / 4 - 1));
    const size_t tb = idx >> 7;
    const int t = (int)(tb / MTOK);
    const int b = (int)(tb & (MTOK - 1));

    const float* g = g_G + tb * 6;
    float ge[6];
    #pragma unroll
    for (int e = 0; e < 6; e++) ge[e] = g[e];

    float4 r = make_float4(0.f, 0.f, 0.f, 0.f);
    #pragma unroll
    for (int e = 0; e < 4; e++) {
        const float4 s = *(const float4*)&g_S[(((size_t)e * MTOK) + b) * NOUT + o4 * 4];
        r.x = fmaf(ge[e], s.x, r.x);
        r.y = fmaf(ge[e], s.y, r.y);
        r.z = fmaf(ge[e], s.z, r.z);
        r.w = fmaf(ge[e], s.w, r.w);
    }
    #pragma unroll
    for (int e = 0; e < 2; e++) {
        const float4 s = *(const float4*)&g_T[(((size_t)(t * 2 + e) * MTOK) + b) * NOUT + o4 * 4];
        r.x = fmaf(ge[4 + e], s.x, r.x);
        r.y = fmaf(ge[4 + e], s.y, r.y);
        r.z = fmaf(ge[4 + e], s.z, r.z);
        r.w = fmaf(ge[4 + e], s.w, r.w);
    }
    *(float4*)(out + idx * 4) = r;
}

// ---------------- launch -----------------------------------------------------
extern "C" void kernel_launch(void* const* d_in, const int* in_sizes, int n_in,
                              void* d_out, int out_size)
{
    const float* task_inputs = (const float*)d_in[0];
    const float* shared_W    = (const float*)d_in[1];
    const float* shared_b    = (const float*)d_in[2];
    const float* task_W      = (const float*)d_in[3];
    const float* task_b      = (const float*)d_in[4];
    const float* gate_W      = (const float*)d_in[5];
    const float* gate_b      = (const float*)d_in[6];
    float* out = (float*)d_out;

    cudaFuncSetAttribute(gemm_mma_kernel,
                         cudaFuncAttributeMaxDynamicSharedMemorySize, SMEM_BYTES);

    // 1) A split (fp32 -> bf16 hi/lo)
    const size_t atot = (size_t)NTASKS * MTOK * KIN;
    asplit_kernel<<<(unsigned)(atot / 8 / 256), 256>>>(task_inputs);

    // 2) W transpose + bf16 hi/lo split
    wprep_kernel<<<dim3(KIN / 32, NOUT / 32, NEXP), 256>>>(shared_W, task_W);

    // 3) gates
    gate_kernel<<<dim3(MTOK / 8, NTASKS), 256>>>(task_inputs, gate_W, gate_b);

    // 4) 10 expert GEMMs, bf16x3 split on HMMA, 16-warp CTA, 3-stage cp.async
    gemm_mma_kernel<<<dim3(NOUT / BN, MTOK / BM, NEXP), 512, SMEM_BYTES>>>(
        shared_b, task_b);

    // 5) gated combine
    const size_t total4 = (size_t)NTASKS * MTOK * NOUT / 4;
    combine_kernel<<<(unsigned)((total4 + 255) / 256), 256>>>(out);
}

// round 7
// speedup vs baseline: 3.0790x; 1.5627x over previous
#include <cuda_runtime.h>
#include <cstdint>
#include <math.h>

#define MTOK 16384
#define NOUT 512
#define KIN  1024
#define NTASKS 3
#define NEXP 10

// ---------------- scratch (device globals; no allocations allowed) ----------
__device__ float g_S[(size_t)4 * MTOK * NOUT];           // shared-expert outs
__device__ float g_T[(size_t)6 * MTOK * NOUT];           // task-expert outs
__device__ float g_G[(size_t)NTASKS * MTOK * 6];         // softmaxed gates
__device__ float g_A32[(size_t)NTASKS * MTOK * KIN];     // A, tf32-rounded
__device__ float g_W32[(size_t)NEXP * NOUT * KIN];       // W^T, tf32-rounded

// ---------------- helpers ----------------------------------------------------
__device__ __forceinline__ uint32_t smem_u32(const void* p) {
    uint32_t a;
    asm("{ .reg .u64 t; cvta.to.shared.u64 t, %1; cvt.u32.u64 %0, t; }"
        : "=r"(a) : "l"(p));
    return a;
}
__device__ __forceinline__ uint32_t SW128(uint32_t o) { return o ^ ((o >> 3) & 0x70); }

__device__ __forceinline__ float tf32r(float x) {
    uint32_t u;
    asm("cvt.rna.tf32.f32 %0, %1;" : "=r"(u) : "f"(x));
    return __uint_as_float(u);
}

__device__ __forceinline__ void cp_async16(uint32_t dst, const void* src) {
    asm volatile("cp.async.cg.shared.global [%0], [%1], 16;"
                 :: "r"(dst), "l"(src) : "memory");
}
#define CP_COMMIT() asm volatile("cp.async.commit_group;" ::: "memory")
#define CP_WAIT2()  asm volatile("cp.async.wait_group 2;" ::: "memory")

__device__ __forceinline__ void ldm_x4(uint32_t* r, uint32_t addr) {
    asm volatile("ldmatrix.sync.aligned.m8n8.x4.shared.b16 {%0,%1,%2,%3}, [%4];"
                 : "=r"(r[0]), "=r"(r[1]), "=r"(r[2]), "=r"(r[3]) : "r"(addr));
}
__device__ __forceinline__ void mma_tf32(float* c, const uint32_t* a, const uint32_t* b) {
    asm volatile("mma.sync.aligned.m16n8k8.row.col.f32.tf32.tf32.f32 "
                 "{%0,%1,%2,%3}, {%4,%5,%6,%7}, {%8,%9}, {%0,%1,%2,%3};"
                 : "+f"(c[0]), "+f"(c[1]), "+f"(c[2]), "+f"(c[3])
                 : "r"(a[0]), "r"(a[1]), "r"(a[2]), "r"(a[3]), "r"(b[0]), "r"(b[1]));
}

// ---------------- A prep: tf32 rounding --------------------------------------
__global__ __launch_bounds__(256)
void aprep_kernel(const float* __restrict__ task_inputs)
{
    const size_t i = ((size_t)blockIdx.x * 256 + threadIdx.x) * 8;
    float4 v0 = *(const float4*)(task_inputs + i);
    float4 v1 = *(const float4*)(task_inputs + i + 4);
    v0.x = tf32r(v0.x); v0.y = tf32r(v0.y); v0.z = tf32r(v0.z); v0.w = tf32r(v0.w);
    v1.x = tf32r(v1.x); v1.y = tf32r(v1.y); v1.z = tf32r(v1.z); v1.w = tf32r(v1.w);
    *(float4*)(g_A32 + i) = v0;
    *(float4*)(g_A32 + i + 4) = v1;
}

// ---------------- W prep: transpose + tf32 round -----------------------------
__global__ __launch_bounds__(256)
void wprep_kernel(const float* __restrict__ shared_W, const float* __restrict__ task_W)
{
    __shared__ float tile[32][33];
    const int e = blockIdx.z;
    const float* W = (e < 4) ? shared_W + (size_t)e * KIN * NOUT
                             : task_W + (size_t)(e - 4) * KIN * NOUT;
    const int k0 = blockIdx.x * 32, n0 = blockIdx.y * 32;
    const int tx = threadIdx.x & 31, ty = threadIdx.x >> 5;

    #pragma unroll
    for (int i = 0; i < 4; i++)
        tile[ty + i * 8][tx] = W[(size_t)(k0 + ty + i * 8) * NOUT + n0 + tx];
    __syncthreads();
    #pragma unroll
    for (int i = 0; i < 4; i++) {
        size_t idx = ((size_t)e * NOUT + (n0 + ty + i * 8)) * KIN + k0 + tx;
        g_W32[idx] = tf32r(tile[tx][ty + i * 8]);
    }
}

// ---------------- TF32 HMMA GEMM: 128x256 CTA, 16 warps, BK=32, 4 stages ----
#define BM 128
#define BN 256
#define BK 32
#define NKT (KIN / BK)     // 32
#define ST_A 0
#define ST_B 16384
#define STAGE_SZ 49152
#define NSTAGE 4
#define SMEM_BYTES (NSTAGE * STAGE_SZ + 1024)

__global__ __launch_bounds__(512, 1)
void gemm_mma_kernel(const float* __restrict__ shared_b,
                     const float* __restrict__ task_b)
{
    extern __shared__ char dsm[];
    __shared__ float sbias[BN];

    const uint32_t raw = smem_u32(dsm);
    const uint32_t sb = (raw + 1023u) & ~1023u;

    const int tid = threadIdx.x;
    const int warp = tid >> 5;
    const int lane = tid & 31;

    const int z = blockIdx.z;
    const int bm0 = blockIdx.y * BM;
    const int bn0 = blockIdx.x * BN;

    size_t a_base;
    const float* bias;
    float* out;
    if (z < 4) {
        a_base = 0;                                  // shared experts: task 0
        bias = shared_b + z * NOUT;
        out = g_S + (size_t)z * MTOK * NOUT;
    } else {
        const int j = z - 4;
        a_base = (size_t)(j >> 1) * MTOK * KIN;
        bias = task_b + j * NOUT;
        out = g_T + (size_t)j * MTOK * NOUT;
    }
    const float* A = g_A32 + a_base;
    const float* W = g_W32 + ((size_t)z * NOUT + bn0) * KIN;

    if (tid < BN) sbias[tid] = bias[bn0 + tid];

    // ---- staging: A 16KB (1024 chunks of 16B, 2/thr), B 32KB (2048, 4/thr) --
    uint32_t a_soff[2];
    const float* a_src[2];
    #pragma unroll
    for (int i = 0; i < 2; i++) {
        int c = tid + 512 * i;
        int row = c >> 3, seg = c & 7;
        a_soff[i] = SW128((uint32_t)(row * 128 + seg * 16));
        a_src[i] = A + (size_t)(bm0 + row) * KIN + seg * 4;
    }
    uint32_t b_soff[4];
    const float* b_src[4];
    #pragma unroll
    for (int i = 0; i < 4; i++) {
        int c = tid + 512 * i;
        int row = c >> 3, seg = c & 7;
        b_soff[i] = SW128((uint32_t)(row * 128 + seg * 16));
        b_src[i] = W + (size_t)row * KIN + seg * 4;
    }

    // warp tiling: 4(M) x 4(N); warp tile 32x64
    const int wm = warp & 3, wn = warp >> 2;
    const int m_base = wm * 32;
    const int n_base = wn * 64;
    const int lg = lane >> 3, r8 = lane & 7;

    // unswizzled lane byte-offsets (add kt4*32 then swizzle in loop)
    uint32_t a_lbase[2];
    #pragma unroll
    for (int mf = 0; mf < 2; mf++)
        a_lbase[mf] = (uint32_t)((m_base + mf * 16 + (lg & 1) * 8 + r8) * 128 + (lg >> 1) * 16);
    uint32_t b_lbase[4];
    #pragma unroll
    for (int p = 0; p < 4; p++)
        b_lbase[p] = (uint32_t)((n_base + p * 16 + (lg >> 1) * 8 + r8) * 128 + (lg & 1) * 16);

    float acc[2][8][4];
    #pragma unroll
    for (int mf = 0; mf < 2; mf++)
        #pragma unroll
        for (int nf = 0; nf < 8; nf++)
            #pragma unroll
            for (int r = 0; r < 4; r++) acc[mf][nf][r] = 0.f;

    auto issue = [&](int kt, int s) {
        const uint32_t sa = sb + s * STAGE_SZ;
        const int ko = kt * BK;
        #pragma unroll
        for (int i = 0; i < 2; i++)
            cp_async16(sa + ST_A + a_soff[i], a_src[i] + ko);
        #pragma unroll
        for (int i = 0; i < 4; i++)
            cp_async16(sa + ST_B + b_soff[i], b_src[i] + ko);
    };

    issue(0, 0); CP_COMMIT();
    issue(1, 1); CP_COMMIT();
    issue(2, 2); CP_COMMIT();

    #pragma unroll 1
    for (int kt = 0; kt < NKT; kt++) {
        CP_WAIT2();
        __syncthreads();

        if (kt + 3 < NKT) issue(kt + 3, (kt + 3) & 3);
        CP_COMMIT();

        const uint32_t ab = sb + (kt & 3) * STAGE_SZ;
        #pragma unroll
        for (int kt4 = 0; kt4 < 4; kt4++) {
            uint32_t afr[2][4], bfr[8][2];
            #pragma unroll
            for (int mf = 0; mf < 2; mf++)
                ldm_x4(afr[mf], ab + ST_A + SW128(a_lbase[mf] + kt4 * 32));
            #pragma unroll
            for (int p = 0; p < 4; p++) {
                uint32_t r[4];
                ldm_x4(r, ab + ST_B + SW128(b_lbase[p] + kt4 * 32));
                bfr[2 * p][0] = r[0];     bfr[2 * p][1] = r[1];
                bfr[2 * p + 1][0] = r[2]; bfr[2 * p + 1][1] = r[3];
            }
            #pragma unroll
            for (int mf = 0; mf < 2; mf++)
                #pragma unroll
                for (int nf = 0; nf < 8; nf++)
                    mma_tf32(acc[mf][nf], afr[mf], bfr[nf]);
        }
    }

    // ---- epilogue: bias + relu + store ----
    const int gq = lane >> 2, i2 = (lane & 3) * 2;
    #pragma unroll
    for (int mf = 0; mf < 2; mf++) {
        const int r0 = bm0 + m_base + mf * 16 + gq;
        #pragma unroll
        for (int nf = 0; nf < 8; nf++) {
            const int cl = n_base + nf * 8 + i2;
            const float b0 = sbias[cl], b1 = sbias[cl + 1];
            float2 v0, v1;
            v0.x = fmaxf(acc[mf][nf][0] + b0, 0.f);
            v0.y = fmaxf(acc[mf][nf][1] + b1, 0.f);
            v1.x = fmaxf(acc[mf][nf][2] + b0, 0.f);
            v1.y = fmaxf(acc[mf][nf][3] + b1, 0.f);
            *(float2*)(out + (size_t)r0 * NOUT + bn0 + cl) = v0;
            *(float2*)(out + (size_t)(r0 + 8) * NOUT + bn0 + cl) = v1;
        }
    }
}

// ---------------- gates (32 tokens/CTA) --------------------------------------
__global__ __launch_bounds__(256)
void gate_kernel(const float* __restrict__ task_inputs,
                 const float* __restrict__ gate_W,
                 const float* __restrict__ gate_b)
{
    __shared__ float Wg[KIN][9];
    const int t = blockIdx.y;
    for (int i = threadIdx.x; i < KIN * 6; i += 256)
        Wg[i / 6][i % 6] = gate_W[(size_t)t * KIN * 6 + i];
    __syncthreads();

    const int warp = threadIdx.x >> 5, lane = threadIdx.x & 31;

    #pragma unroll 1
    for (int w = 0; w < 4; w++) {
        const int b = blockIdx.x * 32 + warp * 4 + w;
        const float* x = task_inputs + ((size_t)t * MTOK + b) * KIN;

        float s[6] = {0.f, 0.f, 0.f, 0.f, 0.f, 0.f};
        #pragma unroll
        for (int i = 0; i < 8; i++) {
            const int k = i * 128 + lane * 4;
            float4 xv = *(const float4*)(x + k);
            float xa[4] = {xv.x, xv.y, xv.z, xv.w};
            #pragma unroll
            for (int j = 0; j < 4; j++)
                #pragma unroll
                for (int e = 0; e < 6; e++)
                    s[e] = fmaf(xa[j], Wg[k + j][e], s[e]);
        }
        #pragma unroll
        for (int off = 16; off > 0; off >>= 1)
            #pragma unroll
            for (int e = 0; e < 6; e++)
                s[e] += __shfl_xor_sync(0xffffffffu, s[e], off);

        if (lane == 0) {
            float l[6], mx = -1e30f;
            #pragma unroll
            for (int e = 0; e < 6; e++) { l[e] = s[e] + gate_b[t * 6 + e]; mx = fmaxf(mx, l[e]); }
            float sum = 0.f;
            #pragma unroll
            for (int e = 0; e < 6; e++) { l[e] = __expf(l[e] - mx); sum += l[e]; }
            float inv = 1.f / sum;
            float* gp = g_G + ((size_t)t * MTOK + b) * 6;
            #pragma unroll
            for (int e = 0; e < 6; e++) gp[e] = l[e] * inv;
        }
    }
}

// ---------------- combine ----------------------------------------------------
__global__ __launch_bounds__(256)
void combine_kernel(float* __restrict__ out)
{
    const size_t idx = (size_t)blockIdx.x * 256 + threadIdx.x;
    const size_t total = (size_t)NTASKS * MTOK * NOUT / 4;
    if (idx >= total) return;
    const int o4 = (int)(idx & (NOUT / 4 - 1));
    const size_t tb = idx >> 7;
    const int t = (int)(tb / MTOK);
    const int b = (int)(tb & (MTOK - 1));

    const float* g = g_G + tb * 6;
    float ge[6];
    #pragma unroll
    for (int e = 0; e < 6; e++) ge[e] = g[e];

    float4 r = make_float4(0.f, 0.f, 0.f, 0.f);
    #pragma unroll
    for (int e = 0; e < 4; e++) {
        const float4 s = *(const float4*)&g_S[(((size_t)e * MTOK) + b) * NOUT + o4 * 4];
        r.x = fmaf(ge[e], s.x, r.x);
        r.y = fmaf(ge[e], s.y, r.y);
        r.z = fmaf(ge[e], s.z, r.z);
        r.w = fmaf(ge[e], s.w, r.w);
    }
    #pragma unroll
    for (int e = 0; e < 2; e++) {
        const float4 s = *(const float4*)&g_T[(((size_t)(t * 2 + e) * MTOK) + b) * NOUT + o4 * 4];
        r.x = fmaf(ge[4 + e], s.x, r.x);
        r.y = fmaf(ge[4 + e], s.y, r.y);
        r.z = fmaf(ge[4 + e], s.z, r.z);
        r.w = fmaf(ge[4 + e], s.w, r.w);
    }
    *(float4*)(out + idx * 4) = r;
}

// ---------------- launch -----------------------------------------------------
extern "C" void kernel_launch(void* const* d_in, const int* in_sizes, int n_in,
                              void* d_out, int out_size)
{
    const float* task_inputs = (const float*)d_in[0];
    const float* shared_W    = (const float*)d_in[1];
    const float* shared_b    = (const float*)d_in[2];
    const float* task_W      = (const float*)d_in[3];
    const float* task_b      = (const float*)d_in[4];
    const float* gate_W      = (const float*)d_in[5];
    const float* gate_b      = (const float*)d_in[6];
    float* out = (float*)d_out;

    cudaFuncSetAttribute(gemm_mma_kernel,
                         cudaFuncAttributeMaxDynamicSharedMemorySize, SMEM_BYTES);

    // 1) A tf32 rounding
    const size_t atot = (size_t)NTASKS * MTOK * KIN;
    aprep_kernel<<<(unsigned)(atot / 8 / 256), 256>>>(task_inputs);

    // 2) W transpose + tf32 rounding
    wprep_kernel<<<dim3(KIN / 32, NOUT / 32, NEXP), 256>>>(shared_W, task_W);

    // 3) gates
    gate_kernel<<<dim3(MTOK / 32, NTASKS), 256>>>(task_inputs, gate_W, gate_b);

    // 4) 10 expert GEMMs, single-pass tf32 HMMA, 4-stage cp.async
    gemm_mma_kernel<<<dim3(NOUT / BN, MTOK / BM, NEXP), 512, SMEM_BYTES>>>(
        shared_b, task_b);

    // 5) gated combine
    const size_t total4 = (size_t)NTASKS * MTOK * NOUT / 4;
    combine_kernel<<<(unsigned)((total4 + 255) / 256), 256>>>(out);
}

// round 8
// speedup vs baseline: 3.2258x; 1.0477x over previous
#include <cuda_runtime.h>
#include <cstdint>
#include <math.h>

#define MTOK 16384
#define NOUT 512
#define KIN  1024
#define NTASKS 3
#define NEXP 10

// ---------------- scratch (device globals; no allocations allowed) ----------
__device__ float g_S[(size_t)4 * MTOK * NOUT];           // shared-expert outs
__device__ float g_T[(size_t)6 * MTOK * NOUT];           // task-expert outs
__device__ float g_G[(size_t)NTASKS * MTOK * 6];         // softmaxed gates
__device__ float g_A32[(size_t)NTASKS * MTOK * KIN];     // A, tf32-rounded
__device__ float g_W32[(size_t)NEXP * NOUT * KIN];       // W^T, tf32-rounded

// ---------------- helpers ----------------------------------------------------
__device__ __forceinline__ uint32_t smem_u32(const void* p) {
    uint32_t a;
    asm("{ .reg .u64 t; cvta.to.shared.u64 t, %1; cvt.u32.u64 %0, t; }"
        : "=r"(a) : "l"(p));
    return a;
}
__device__ __forceinline__ uint32_t SW128(uint32_t o) { return o ^ ((o >> 3) & 0x70); }

__device__ __forceinline__ float tf32r(float x) {
    uint32_t u;
    asm("cvt.rna.tf32.f32 %0, %1;" : "=r"(u) : "f"(x));
    return __uint_as_float(u);
}

__device__ __forceinline__ void cp_async16(uint32_t dst, const void* src) {
    asm volatile("cp.async.cg.shared.global [%0], [%1], 16;"
                 :: "r"(dst), "l"(src) : "memory");
}
#define CP_COMMIT() asm volatile("cp.async.commit_group;" ::: "memory")
#define CP_WAIT1()  asm volatile("cp.async.wait_group 1;" ::: "memory")

__device__ __forceinline__ void ldm_x4(uint32_t* r, uint32_t addr) {
    asm volatile("ldmatrix.sync.aligned.m8n8.x4.shared.b16 {%0,%1,%2,%3}, [%4];"
                 : "=r"(r[0]), "=r"(r[1]), "=r"(r[2]), "=r"(r[3]) : "r"(addr));
}
__device__ __forceinline__ void mma_tf32(float* c, const uint32_t* a, const uint32_t* b) {
    asm volatile("mma.sync.aligned.m16n8k8.row.col.f32.tf32.tf32.f32 "
                 "{%0,%1,%2,%3}, {%4,%5,%6,%7}, {%8,%9}, {%0,%1,%2,%3};"
                 : "+f"(c[0]), "+f"(c[1]), "+f"(c[2]), "+f"(c[3])
                 : "r"(a[0]), "r"(a[1]), "r"(a[2]), "r"(a[3]), "r"(b[0]), "r"(b[1]));
}

// ---------------- A prep: tf32 rounding --------------------------------------
__global__ __launch_bounds__(256)
void aprep_kernel(const float* __restrict__ task_inputs)
{
    const size_t i = ((size_t)blockIdx.x * 256 + threadIdx.x) * 8;
    float4 v0 = *(const float4*)(task_inputs + i);
    float4 v1 = *(const float4*)(task_inputs + i + 4);
    v0.x = tf32r(v0.x); v0.y = tf32r(v0.y); v0.z = tf32r(v0.z); v0.w = tf32r(v0.w);
    v1.x = tf32r(v1.x); v1.y = tf32r(v1.y); v1.z = tf32r(v1.z); v1.w = tf32r(v1.w);
    *(float4*)(g_A32 + i) = v0;
    *(float4*)(g_A32 + i + 4) = v1;
}

// ---------------- W prep: transpose + tf32 round -----------------------------
__global__ __launch_bounds__(256)
void wprep_kernel(const float* __restrict__ shared_W, const float* __restrict__ task_W)
{
    __shared__ float tile[32][33];
    const int e = blockIdx.z;
    const float* W = (e < 4) ? shared_W + (size_t)e * KIN * NOUT
                             : task_W + (size_t)(e - 4) * KIN * NOUT;
    const int k0 = blockIdx.x * 32, n0 = blockIdx.y * 32;
    const int tx = threadIdx.x & 31, ty = threadIdx.x >> 5;

    #pragma unroll
    for (int i = 0; i < 4; i++)
        tile[ty + i * 8][tx] = W[(size_t)(k0 + ty + i * 8) * NOUT + n0 + tx];
    __syncthreads();
    #pragma unroll
    for (int i = 0; i < 4; i++) {
        size_t idx = ((size_t)e * NOUT + (n0 + ty + i * 8)) * KIN + k0 + tx;
        g_W32[idx] = tf32r(tile[tx][ty + i * 8]);
    }
}

// ---------------- TF32 HMMA GEMM: 128x128 CTA, 8 warps, BK=32, 3 stages -----
// 2 CTAs/SM: barrier windows of the two CTAs interleave -> tensor pipe stays fed
#define BM 128
#define BN 128
#define BK 32
#define NKT (KIN / BK)     // 32
#define ST_A 0
#define ST_B 16384
#define STAGE_SZ 32768
#define NSTAGE 3
#define SMEM_BYTES (NSTAGE * STAGE_SZ + 1024)

__global__ __launch_bounds__(256, 2)
void gemm_mma_kernel(const float* __restrict__ shared_b,
                     const float* __restrict__ task_b)
{
    extern __shared__ char dsm[];
    __shared__ float sbias[BN];

    const uint32_t raw = smem_u32(dsm);
    const uint32_t sb = (raw + 1023u) & ~1023u;

    const int tid = threadIdx.x;
    const int warp = tid >> 5;
    const int lane = tid & 31;

    const int z = blockIdx.z;
    const int bm0 = blockIdx.y * BM;
    const int bn0 = blockIdx.x * BN;

    size_t a_base;
    const float* bias;
    float* out;
    if (z < 4) {
        a_base = 0;                                  // shared experts: task 0
        bias = shared_b + z * NOUT;
        out = g_S + (size_t)z * MTOK * NOUT;
    } else {
        const int j = z - 4;
        a_base = (size_t)(j >> 1) * MTOK * KIN;
        bias = task_b + j * NOUT;
        out = g_T + (size_t)j * MTOK * NOUT;
    }
    const float* A = g_A32 + a_base;
    const float* W = g_W32 + ((size_t)z * NOUT + bn0) * KIN;

    if (tid < BN) sbias[tid] = bias[bn0 + tid];

    // ---- staging: A 16KB (1024 x 16B chunks, 4/thr), B 16KB (4/thr) --------
    uint32_t a_soff[4], b_soff[4];
    const float* a_src[4];
    const float* b_src[4];
    #pragma unroll
    for (int i = 0; i < 4; i++) {
        int c = tid + 256 * i;
        int row = c >> 3, seg = c & 7;
        uint32_t so = SW128((uint32_t)(row * 128 + seg * 16));
        a_soff[i] = so;
        b_soff[i] = so;
        a_src[i] = A + (size_t)(bm0 + row) * KIN + seg * 4;
        b_src[i] = W + (size_t)row * KIN + seg * 4;
    }

    // warp tiling: 2(M) x 4(N); warp tile 64x32
    const int wm = warp & 1, wn = warp >> 1;
    const int m_base = wm * 64;
    const int n_base = wn * 32;
    const int lg = lane >> 3, r8 = lane & 7;

    uint32_t a_lbase[4];
    #pragma unroll
    for (int mf = 0; mf < 4; mf++)
        a_lbase[mf] = (uint32_t)((m_base + mf * 16 + (lg & 1) * 8 + r8) * 128 + (lg >> 1) * 16);
    uint32_t b_lbase[2];
    #pragma unroll
    for (int p = 0; p < 2; p++)
        b_lbase[p] = (uint32_t)((n_base + p * 16 + (lg >> 1) * 8 + r8) * 128 + (lg & 1) * 16);

    float acc[4][4][4];
    #pragma unroll
    for (int mf = 0; mf < 4; mf++)
        #pragma unroll
        for (int nf = 0; nf < 4; nf++)
            #pragma unroll
            for (int r = 0; r < 4; r++) acc[mf][nf][r] = 0.f;

    auto issue = [&](int kt, int s) {
        const uint32_t sa = sb + s * STAGE_SZ;
        const int ko = kt * BK;
        #pragma unroll
        for (int i = 0; i < 4; i++)
            cp_async16(sa + ST_A + a_soff[i], a_src[i] + ko);
        #pragma unroll
        for (int i = 0; i < 4; i++)
            cp_async16(sa + ST_B + b_soff[i], b_src[i] + ko);
    };

    issue(0, 0); CP_COMMIT();
    issue(1, 1); CP_COMMIT();

    int buf = 0, nxt = 2;
    #pragma unroll 1
    for (int kt = 0; kt < NKT; kt++) {
        CP_WAIT1();
        __syncthreads();

        if (kt + 2 < NKT) issue(kt + 2, nxt);
        CP_COMMIT();

        const uint32_t ab = sb + buf * STAGE_SZ;
        buf = (buf == 2) ? 0 : buf + 1;
        nxt = (nxt == 2) ? 0 : nxt + 1;

        #pragma unroll
        for (int kt4 = 0; kt4 < 4; kt4++) {
            uint32_t afr[4][4], bfr[4][2];
            #pragma unroll
            for (int p = 0; p < 2; p++) {
                uint32_t r[4];
                ldm_x4(r, ab + ST_B + SW128(b_lbase[p] + kt4 * 32));
                bfr[2 * p][0] = r[0];     bfr[2 * p][1] = r[1];
                bfr[2 * p + 1][0] = r[2]; bfr[2 * p + 1][1] = r[3];
            }
            #pragma unroll
            for (int mf = 0; mf < 4; mf++)
                ldm_x4(afr[mf], ab + ST_A + SW128(a_lbase[mf] + kt4 * 32));
            #pragma unroll
            for (int mf = 0; mf < 4; mf++)
                #pragma unroll
                for (int nf = 0; nf < 4; nf++)
                    mma_tf32(acc[mf][nf], afr[mf], bfr[nf]);
        }
    }

    // ---- epilogue: bias + relu + store ----
    const int gq = lane >> 2, i2 = (lane & 3) * 2;
    #pragma unroll
    for (int mf = 0; mf < 4; mf++) {
        const int r0 = bm0 + m_base + mf * 16 + gq;
        #pragma unroll
        for (int nf = 0; nf < 4; nf++) {
            const int cl = n_base + nf * 8 + i2;
            const float b0 = sbias[cl], b1 = sbias[cl + 1];
            float2 v0, v1;
            v0.x = fmaxf(acc[mf][nf][0] + b0, 0.f);
            v0.y = fmaxf(acc[mf][nf][1] + b1, 0.f);
            v1.x = fmaxf(acc[mf][nf][2] + b0, 0.f);
            v1.y = fmaxf(acc[mf][nf][3] + b1, 0.f);
            *(float2*)(out + (size_t)r0 * NOUT + bn0 + cl) = v0;
            *(float2*)(out + (size_t)(r0 + 8) * NOUT + bn0 + cl) = v1;
        }
    }
}

// ---------------- gates (32 tokens/CTA) --------------------------------------
__global__ __launch_bounds__(256)
void gate_kernel(const float* __restrict__ task_inputs,
                 const float* __restrict__ gate_W,
                 const float* __restrict__ gate_b)
{
    __shared__ float Wg[KIN][9];
    const int t = blockIdx.y;
    for (int i = threadIdx.x; i < KIN * 6; i += 256)
        Wg[i / 6][i % 6] = gate_W[(size_t)t * KIN * 6 + i];
    __syncthreads();

    const int warp = threadIdx.x >> 5, lane = threadIdx.x & 31;

    #pragma unroll 1
    for (int w = 0; w < 4; w++) {
        const int b = blockIdx.x * 32 + warp * 4 + w;
        const float* x = task_inputs + ((size_t)t * MTOK + b) * KIN;

        float s[6] = {0.f, 0.f, 0.f, 0.f, 0.f, 0.f};
        #pragma unroll
        for (int i = 0; i < 8; i++) {
            const int k = i * 128 + lane * 4;
            float4 xv = *(const float4*)(x + k);
            float xa[4] = {xv.x, xv.y, xv.z, xv.w};
            #pragma unroll
            for (int j = 0; j < 4; j++)
                #pragma unroll
                for (int e = 0; e < 6; e++)
                    s[e] = fmaf(xa[j], Wg[k + j][e], s[e]);
        }
        #pragma unroll
        for (int off = 16; off > 0; off >>= 1)
            #pragma unroll
            for (int e = 0; e < 6; e++)
                s[e] += __shfl_xor_sync(0xffffffffu, s[e], off);

        if (lane == 0) {
            float l[6], mx = -1e30f;
            #pragma unroll
            for (int e = 0; e < 6; e++) { l[e] = s[e] + gate_b[t * 6 + e]; mx = fmaxf(mx, l[e]); }
            float sum = 0.f;
            #pragma unroll
            for (int e = 0; e < 6; e++) { l[e] = __expf(l[e] - mx); sum += l[e]; }
            float inv = 1.f / sum;
            float* gp = g_G + ((size_t)t * MTOK + b) * 6;
            #pragma unroll
            for (int e = 0; e < 6; e++) gp[e] = l[e] * inv;
        }
    }
}

// ---------------- combine: all 3 tasks per thread (S read once) --------------
__global__ __launch_bounds__(256)
void combine_kernel(float* __restrict__ out)
{
    const size_t idx = (size_t)blockIdx.x * 256 + threadIdx.x;   // b*128 + o4
    const int o4 = (int)(idx & (NOUT / 4 - 1));                  // 0..127
    const int b = (int)(idx >> 7);

    float ge[NTASKS][6];
    #pragma unroll
    for (int t = 0; t < NTASKS; t++) {
        const float* g = g_G + ((size_t)t * MTOK + b) * 6;
        #pragma unroll
        for (int e = 0; e < 6; e++) ge[t][e] = g[e];
    }

    float4 r[NTASKS];
    #pragma unroll
    for (int t = 0; t < NTASKS; t++) r[t] = make_float4(0.f, 0.f, 0.f, 0.f);

    #pragma unroll
    for (int e = 0; e < 4; e++) {
        const float4 s = *(const float4*)&g_S[(((size_t)e * MTOK) + b) * NOUT + o4 * 4];
        #pragma unroll
        for (int t = 0; t < NTASKS; t++) {
            r[t].x = fmaf(ge[t][e], s.x, r[t].x);
            r[t].y = fmaf(ge[t][e], s.y, r[t].y);
            r[t].z = fmaf(ge[t][e], s.z, r[t].z);
            r[t].w = fmaf(ge[t][e], s.w, r[t].w);
        }
    }
    #pragma unroll
    for (int t = 0; t < NTASKS; t++) {
        #pragma unroll
        for (int e = 0; e < 2; e++) {
            const float4 s = *(const float4*)&g_T[(((size_t)(t * 2 + e) * MTOK) + b) * NOUT + o4 * 4];
            r[t].x = fmaf(ge[t][4 + e], s.x, r[t].x);
            r[t].y = fmaf(ge[t][4 + e], s.y, r[t].y);
            r[t].z = fmaf(ge[t][4 + e], s.z, r[t].z);
            r[t].w = fmaf(ge[t][4 + e], s.w, r[t].w);
        }
        *(float4*)(out + (((size_t)t * MTOK + b) * NOUT) + o4 * 4) = r[t];
    }
}

// ---------------- launch -----------------------------------------------------
extern "C" void kernel_launch(void* const* d_in, const int* in_sizes, int n_in,
                              void* d_out, int out_size)
{
    const float* task_inputs = (const float*)d_in[0];
    const float* shared_W    = (const float*)d_in[1];
    const float* shared_b    = (const float*)d_in[2];
    const float* task_W      = (const float*)d_in[3];
    const float* task_b      = (const float*)d_in[4];
    const float* gate_W      = (const float*)d_in[5];
    const float* gate_b      = (const float*)d_in[6];
    float* out = (float*)d_out;

    cudaFuncSetAttribute(gemm_mma_kernel,
                         cudaFuncAttributeMaxDynamicSharedMemorySize, SMEM_BYTES);

    // 1) A tf32 rounding
    const size_t atot = (size_t)NTASKS * MTOK * KIN;
    aprep_kernel<<<(unsigned)(atot / 8 / 256), 256>>>(task_inputs);

    // 2) W transpose + tf32 rounding
    wprep_kernel<<<dim3(KIN / 32, NOUT / 32, NEXP), 256>>>(shared_W, task_W);

    // 3) gates
    gate_kernel<<<dim3(MTOK / 32, NTASKS), 256>>>(task_inputs, gate_W, gate_b);

    // 4) 10 expert GEMMs, single-pass tf32 HMMA, 2 CTAs/SM
    gemm_mma_kernel<<<dim3(NOUT / BN, MTOK / BM, NEXP), 256, SMEM_BYTES>>>(
        shared_b, task_b);

    // 5) gated combine (all 3 tasks per thread; S read once)
    const size_t totalc = (size_t)MTOK * (NOUT / 4);
    combine_kernel<<<(unsigned)(totalc / 256), 256>>>(out);
}

// round 9
// speedup vs baseline: 3.2287x; 1.0009x over previous
#include <cuda_runtime.h>
#include <cstdint>
#include <math.h>

#define MTOK 16384
#define NOUT 512
#define KIN  1024
#define NTASKS 3
#define NEXP 10

// ---------------- scratch (device globals; no allocations allowed) ----------
__device__ float g_S[(size_t)4 * MTOK * NOUT];           // shared-expert outs
__device__ float g_T[(size_t)6 * MTOK * NOUT];           // task-expert outs
__device__ float g_G[(size_t)NTASKS * MTOK * 6];         // softmaxed gates
__device__ float g_W32[(size_t)NEXP * NOUT * KIN];       // W^T, tf32-rounded

// ---------------- helpers ----------------------------------------------------
__device__ __forceinline__ uint32_t smem_u32(const void* p) {
    uint32_t a;
    asm("{ .reg .u64 t; cvta.to.shared.u64 t, %1; cvt.u32.u64 %0, t; }"
        : "=r"(a) : "l"(p));
    return a;
}
__device__ __forceinline__ uint32_t SW128(uint32_t o) { return o ^ ((o >> 3) & 0x70); }

__device__ __forceinline__ float tf32r(float x) {
    uint32_t u;
    asm("cvt.rna.tf32.f32 %0, %1;" : "=r"(u) : "f"(x));
    return __uint_as_float(u);
}

__device__ __forceinline__ void cp_async16(uint32_t dst, const void* src) {
    asm volatile("cp.async.cg.shared.global [%0], [%1], 16;"
                 :: "r"(dst), "l"(src) : "memory");
}
#define CP_COMMIT() asm volatile("cp.async.commit_group;" ::: "memory")
#define CP_WAIT1()  asm volatile("cp.async.wait_group 1;" ::: "memory")

__device__ __forceinline__ void ldm_x4(uint32_t* r, uint32_t addr) {
    asm volatile("ldmatrix.sync.aligned.m8n8.x4.shared.b16 {%0,%1,%2,%3}, [%4];"
                 : "=r"(r[0]), "=r"(r[1]), "=r"(r[2]), "=r"(r[3]) : "r"(addr));
}
__device__ __forceinline__ void mma_tf32(float* c, const uint32_t* a, const uint32_t* b) {
    asm volatile("mma.sync.aligned.m16n8k8.row.col.f32.tf32.tf32.f32 "
                 "{%0,%1,%2,%3}, {%4,%5,%6,%7}, {%8,%9}, {%0,%1,%2,%3};"
                 : "+f"(c[0]), "+f"(c[1]), "+f"(c[2]), "+f"(c[3])
                 : "r"(a[0]), "r"(a[1]), "r"(a[2]), "r"(a[3]), "r"(b[0]), "r"(b[1]));
}

// ---------------- W prep: transpose + tf32 round -----------------------------
__global__ __launch_bounds__(256)
void wprep_kernel(const float* __restrict__ shared_W, const float* __restrict__ task_W)
{
    __shared__ float tile[32][33];
    const int e = blockIdx.z;
    const float* W = (e < 4) ? shared_W + (size_t)e * KIN * NOUT
                             : task_W + (size_t)(e - 4) * KIN * NOUT;
    const int k0 = blockIdx.x * 32, n0 = blockIdx.y * 32;
    const int tx = threadIdx.x & 31, ty = threadIdx.x >> 5;

    #pragma unroll
    for (int i = 0; i < 4; i++)
        tile[ty + i * 8][tx] = W[(size_t)(k0 + ty + i * 8) * NOUT + n0 + tx];
    __syncthreads();
    #pragma unroll
    for (int i = 0; i < 4; i++) {
        size_t idx = ((size_t)e * NOUT + (n0 + ty + i * 8)) * KIN + k0 + tx;
        g_W32[idx] = tf32r(tile[tx][ty + i * 8]);
    }
}

// ---------------- fused GEMM (z<10) + gates (z==10) --------------------------
// GEMM: 128x128 CTA, 8 warps, BK=32, 3 stages, 2 CTAs/SM. A read raw fp32
// (HW truncates to tf32). Gate blocks use the same dynamic smem for gate_W.
#define BM 128
#define BN 128
#define BK 32
#define NKT (KIN / BK)     // 32
#define ST_A 0
#define ST_B 16384
#define STAGE_SZ 32768
#define NSTAGE 3
#define SMEM_BYTES (NSTAGE * STAGE_SZ + 1024)

__global__ __launch_bounds__(256, 2)
void gemm_mma_kernel(const float* __restrict__ task_inputs,
                     const float* __restrict__ shared_b,
                     const float* __restrict__ task_b,
                     const float* __restrict__ gate_W,
                     const float* __restrict__ gate_b)
{
    extern __shared__ char dsm[];
    __shared__ float sbias[BN];

    const int tid = threadIdx.x;
    const int warp = tid >> 5;
    const int lane = tid & 31;
    const int z = blockIdx.z;

    // ======================= gate path (z == 10) ============================
    if (z == 10) {
        float* Wg = (float*)dsm;                       // [KIN][9] padded
        const int blk = blockIdx.y * gridDim.x + blockIdx.x;   // 0..511
        #pragma unroll 1
        for (int t = 0; t < NTASKS; t++) {
            __syncthreads();
            for (int i = tid; i < KIN * 6; i += 256)
                Wg[(i / 6) * 9 + (i % 6)] = gate_W[(size_t)t * KIN * 6 + i];
            __syncthreads();

            #pragma unroll 1
            for (int w = 0; w < 4; w++) {
                const int b = blk * 32 + warp * 4 + w;
                const float* x = task_inputs + ((size_t)t * MTOK + b) * KIN;

                float s[6] = {0.f, 0.f, 0.f, 0.f, 0.f, 0.f};
                #pragma unroll
                for (int i = 0; i < 8; i++) {
                    const int k = i * 128 + lane * 4;
                    float4 xv = *(const float4*)(x + k);
                    float xa[4] = {xv.x, xv.y, xv.z, xv.w};
                    #pragma unroll
                    for (int j = 0; j < 4; j++)
                        #pragma unroll
                        for (int e = 0; e < 6; e++)
                            s[e] = fmaf(xa[j], Wg[(k + j) * 9 + e], s[e]);
                }
                #pragma unroll
                for (int off = 16; off > 0; off >>= 1)
                    #pragma unroll
                    for (int e = 0; e < 6; e++)
                        s[e] += __shfl_xor_sync(0xffffffffu, s[e], off);

                if (lane == 0) {
                    float l[6], mx = -1e30f;
                    #pragma unroll
                    for (int e = 0; e < 6; e++) { l[e] = s[e] + gate_b[t * 6 + e]; mx = fmaxf(mx, l[e]); }
                    float sum = 0.f;
                    #pragma unroll
                    for (int e = 0; e < 6; e++) { l[e] = __expf(l[e] - mx); sum += l[e]; }
                    float inv = 1.f / sum;
                    float* gp = g_G + ((size_t)t * MTOK + b) * 6;
                    #pragma unroll
                    for (int e = 0; e < 6; e++) gp[e] = l[e] * inv;
                }
            }
        }
        return;
    }

    // ======================= GEMM path (z < 10) =============================
    const uint32_t raw = smem_u32(dsm);
    const uint32_t sb = (raw + 1023u) & ~1023u;

    const int bm0 = blockIdx.y * BM;
    const int bn0 = blockIdx.x * BN;

    size_t a_base;
    const float* bias;
    float* out;
    if (z < 4) {
        a_base = 0;                                  // shared experts: task 0
        bias = shared_b + z * NOUT;
        out = g_S + (size_t)z * MTOK * NOUT;
    } else {
        const int j = z - 4;
        a_base = (size_t)(j >> 1) * MTOK * KIN;
        bias = task_b + j * NOUT;
        out = g_T + (size_t)j * MTOK * NOUT;
    }
    const float* A = task_inputs + a_base;           // raw fp32; HW tf32-truncates
    const float* W = g_W32 + ((size_t)z * NOUT + bn0) * KIN;

    if (tid < BN) sbias[tid] = bias[bn0 + tid];

    // ---- staging: A 16KB (1024 x 16B chunks, 4/thr), B 16KB (4/thr) --------
    uint32_t a_soff[4], b_soff[4];
    const float* a_src[4];
    const float* b_src[4];
    #pragma unroll
    for (int i = 0; i < 4; i++) {
        int c = tid + 256 * i;
        int row = c >> 3, seg = c & 7;
        uint32_t so = SW128((uint32_t)(row * 128 + seg * 16));
        a_soff[i] = so;
        b_soff[i] = so;
        a_src[i] = A + (size_t)(bm0 + row) * KIN + seg * 4;
        b_src[i] = W + (size_t)row * KIN + seg * 4;
    }

    // warp tiling: 2(M) x 4(N); warp tile 64x32
    const int wm = warp & 1, wn = warp >> 1;
    const int m_base = wm * 64;
    const int n_base = wn * 32;
    const int lg = lane >> 3, r8 = lane & 7;

    uint32_t a_lbase[4];
    #pragma unroll
    for (int mf = 0; mf < 4; mf++)
        a_lbase[mf] = (uint32_t)((m_base + mf * 16 + (lg & 1) * 8 + r8) * 128 + (lg >> 1) * 16);
    uint32_t b_lbase[2];
    #pragma unroll
    for (int p = 0; p < 2; p++)
        b_lbase[p] = (uint32_t)((n_base + p * 16 + (lg >> 1) * 8 + r8) * 128 + (lg & 1) * 16);

    float acc[4][4][4];
    #pragma unroll
    for (int mf = 0; mf < 4; mf++)
        #pragma unroll
        for (int nf = 0; nf < 4; nf++)
            #pragma unroll
            for (int r = 0; r < 4; r++) acc[mf][nf][r] = 0.f;

    auto issue = [&](int kt, int s) {
        const uint32_t sa = sb + s * STAGE_SZ;
        const int ko = kt * BK;
        #pragma unroll
        for (int i = 0; i < 4; i++)
            cp_async16(sa + ST_A + a_soff[i], a_src[i] + ko);
        #pragma unroll
        for (int i = 0; i < 4; i++)
            cp_async16(sa + ST_B + b_soff[i], b_src[i] + ko);
    };

    issue(0, 0); CP_COMMIT();
    issue(1, 1); CP_COMMIT();

    int buf = 0, nxt = 2;
    #pragma unroll 1
    for (int kt = 0; kt < NKT; kt++) {
        CP_WAIT1();
        __syncthreads();

        if (kt + 2 < NKT) issue(kt + 2, nxt);
        CP_COMMIT();

        const uint32_t ab = sb + buf * STAGE_SZ;
        buf = (buf == 2) ? 0 : buf + 1;
        nxt = (nxt == 2) ? 0 : nxt + 1;

        #pragma unroll
        for (int kt4 = 0; kt4 < 4; kt4++) {
            uint32_t afr[4][4], bfr[4][2];
            #pragma unroll
            for (int p = 0; p < 2; p++) {
                uint32_t r[4];
                ldm_x4(r, ab + ST_B + SW128(b_lbase[p] + kt4 * 32));
                bfr[2 * p][0] = r[0];     bfr[2 * p][1] = r[1];
                bfr[2 * p + 1][0] = r[2]; bfr[2 * p + 1][1] = r[3];
            }
            #pragma unroll
            for (int mf = 0; mf < 4; mf++)
                ldm_x4(afr[mf], ab + ST_A + SW128(a_lbase[mf] + kt4 * 32));
            #pragma unroll
            for (int mf = 0; mf < 4; mf++)
                #pragma unroll
                for (int nf = 0; nf < 4; nf++)
                    mma_tf32(acc[mf][nf], afr[mf], bfr[nf]);
        }
    }

    // ---- epilogue: bias + relu + store ----
    const int gq = lane >> 2, i2 = (lane & 3) * 2;
    #pragma unroll
    for (int mf = 0; mf < 4; mf++) {
        const int r0 = bm0 + m_base + mf * 16 + gq;
        #pragma unroll
        for (int nf = 0; nf < 4; nf++) {
            const int cl = n_base + nf * 8 + i2;
            const float b0 = sbias[cl], b1 = sbias[cl + 1];
            float2 v0, v1;
            v0.x = fmaxf(acc[mf][nf][0] + b0, 0.f);
            v0.y = fmaxf(acc[mf][nf][1] + b1, 0.f);
            v1.x = fmaxf(acc[mf][nf][2] + b0, 0.f);
            v1.y = fmaxf(acc[mf][nf][3] + b1, 0.f);
            *(float2*)(out + (size_t)r0 * NOUT + bn0 + cl) = v0;
            *(float2*)(out + (size_t)(r0 + 8) * NOUT + bn0 + cl) = v1;
        }
    }
}

// ---------------- combine: all 3 tasks per thread (S read once) --------------
__global__ __launch_bounds__(256)
void combine_kernel(float* __restrict__ out)
{
    const size_t idx = (size_t)blockIdx.x * 256 + threadIdx.x;   // b*128 + o4
    const int o4 = (int)(idx & (NOUT / 4 - 1));                  // 0..127
    const int b = (int)(idx >> 7);

    float ge[NTASKS][6];
    #pragma unroll
    for (int t = 0; t < NTASKS; t++) {
        const float* g = g_G + ((size_t)t * MTOK + b) * 6;
        #pragma unroll
        for (int e = 0; e < 6; e++) ge[t][e] = g[e];
    }

    float4 r[NTASKS];
    #pragma unroll
    for (int t = 0; t < NTASKS; t++) r[t] = make_float4(0.f, 0.f, 0.f, 0.f);

    #pragma unroll
    for (int e = 0; e < 4; e++) {
        const float4 s = *(const float4*)&g_S[(((size_t)e * MTOK) + b) * NOUT + o4 * 4];
        #pragma unroll
        for (int t = 0; t < NTASKS; t++) {
            r[t].x = fmaf(ge[t][e], s.x, r[t].x);
            r[t].y = fmaf(ge[t][e], s.y, r[t].y);
            r[t].z = fmaf(ge[t][e], s.z, r[t].z);
            r[t].w = fmaf(ge[t][e], s.w, r[t].w);
        }
    }
    #pragma unroll
    for (int t = 0; t < NTASKS; t++) {
        #pragma unroll
        for (int e = 0; e < 2; e++) {
            const float4 s = *(const float4*)&g_T[(((size_t)(t * 2 + e) * MTOK) + b) * NOUT + o4 * 4];
            r[t].x = fmaf(ge[t][4 + e], s.x, r[t].x);
            r[t].y = fmaf(ge[t][4 + e], s.y, r[t].y);
            r[t].z = fmaf(ge[t][4 + e], s.z, r[t].z);
            r[t].w = fmaf(ge[t][4 + e], s.w, r[t].w);
        }
        *(float4*)(out + (((size_t)t * MTOK + b) * NOUT) + o4 * 4) = r[t];
    }
}

// ---------------- launch -----------------------------------------------------
extern "C" void kernel_launch(void* const* d_in, const int* in_sizes, int n_in,
                              void* d_out, int out_size)
{
    const float* task_inputs = (const float*)d_in[0];
    const float* shared_W    = (const float*)d_in[1];
    const float* shared_b    = (const float*)d_in[2];
    const float* task_W      = (const float*)d_in[3];
    const float* task_b      = (const float*)d_in[4];
    const float* gate_W      = (const float*)d_in[5];
    const float* gate_b      = (const float*)d_in[6];
    float* out = (float*)d_out;

    cudaFuncSetAttribute(gemm_mma_kernel,
                         cudaFuncAttributeMaxDynamicSharedMemorySize, SMEM_BYTES);

    // 1) W transpose + tf32 rounding
    wprep_kernel<<<dim3(KIN / 32, NOUT / 32, NEXP), 256>>>(shared_W, task_W);

    // 2) fused: 10 expert GEMMs (z<10) + gates (z==10), A fed raw fp32
    gemm_mma_kernel<<<dim3(NOUT / BN, MTOK / BM, NEXP + 1), 256, SMEM_BYTES>>>(
        task_inputs, shared_b, task_b, gate_W, gate_b);

    // 3) gated combine (all 3 tasks per thread; S read once)
    const size_t totalc = (size_t)MTOK * (NOUT / 4);
    combine_kernel<<<(unsigned)(totalc / 256), 256>>>(out);
}

// round 10
// speedup vs baseline: 3.2802x; 1.0159x over previous
#include <cuda_runtime.h>
#include <cuda_fp16.h>
#include <cstdint>
#include <math.h>

#define MTOK 16384
#define NOUT 512
#define KIN  1024
#define NTASKS 3
#define NEXP 10

// ---------------- scratch (device globals; no allocations allowed) ----------
__device__ __half g_S[(size_t)4 * MTOK * NOUT];          // shared-expert outs (fp16)
__device__ __half g_T[(size_t)6 * MTOK * NOUT];          // task-expert outs (fp16)
__device__ float g_G[(size_t)NTASKS * MTOK * 6];         // softmaxed gates
__device__ float g_W32[(size_t)NEXP * NOUT * KIN];       // W^T, tf32-rounded

// ---------------- helpers ----------------------------------------------------
__device__ __forceinline__ uint32_t smem_u32(const void* p) {
    uint32_t a;
    asm("{ .reg .u64 t; cvta.to.shared.u64 t, %1; cvt.u32.u64 %0, t; }"
        : "=r"(a) : "l"(p));
    return a;
}
__device__ __forceinline__ uint32_t SW128(uint32_t o) { return o ^ ((o >> 3) & 0x70); }

__device__ __forceinline__ float tf32r(float x) {
    uint32_t u;
    asm("cvt.rna.tf32.f32 %0, %1;" : "=r"(u) : "f"(x));
    return __uint_as_float(u);
}

__device__ __forceinline__ void cp_async16(uint32_t dst, const void* src) {
    asm volatile("cp.async.cg.shared.global [%0], [%1], 16;"
                 :: "r"(dst), "l"(src) : "memory");
}
#define CP_COMMIT() asm volatile("cp.async.commit_group;" ::: "memory")
#define CP_WAIT1()  asm volatile("cp.async.wait_group 1;" ::: "memory")

__device__ __forceinline__ void ldm_x4(uint32_t* r, uint32_t addr) {
    asm volatile("ldmatrix.sync.aligned.m8n8.x4.shared.b16 {%0,%1,%2,%3}, [%4];"
                 : "=r"(r[0]), "=r"(r[1]), "=r"(r[2]), "=r"(r[3]) : "r"(addr));
}
__device__ __forceinline__ void mma_tf32(float* c, const uint32_t* a, const uint32_t* b) {
    asm volatile("mma.sync.aligned.m16n8k8.row.col.f32.tf32.tf32.f32 "
                 "{%0,%1,%2,%3}, {%4,%5,%6,%7}, {%8,%9}, {%0,%1,%2,%3};"
                 : "+f"(c[0]), "+f"(c[1]), "+f"(c[2]), "+f"(c[3])
                 : "r"(a[0]), "r"(a[1]), "r"(a[2]), "r"(a[3]), "r"(b[0]), "r"(b[1]));
}

// ---------------- W prep: transpose + tf32 round -----------------------------
__global__ __launch_bounds__(256)
void wprep_kernel(const float* __restrict__ shared_W, const float* __restrict__ task_W)
{
    __shared__ float tile[32][33];
    const int e = blockIdx.z;
    const float* W = (e < 4) ? shared_W + (size_t)e * KIN * NOUT
                             : task_W + (size_t)(e - 4) * KIN * NOUT;
    const int k0 = blockIdx.x * 32, n0 = blockIdx.y * 32;
    const int tx = threadIdx.x & 31, ty = threadIdx.x >> 5;

    #pragma unroll
    for (int i = 0; i < 4; i++)
        tile[ty + i * 8][tx] = W[(size_t)(k0 + ty + i * 8) * NOUT + n0 + tx];
    __syncthreads();
    #pragma unroll
    for (int i = 0; i < 4; i++) {
        size_t idx = ((size_t)e * NOUT + (n0 + ty + i * 8)) * KIN + k0 + tx;
        g_W32[idx] = tf32r(tile[tx][ty + i * 8]);
    }
}

// ---------------- fused GEMM (z<10) + gates (z==10) --------------------------
#define BM 128
#define BN 128
#define BK 32
#define NKT (KIN / BK)     // 32
#define ST_A 0
#define ST_B 16384
#define STAGE_SZ 32768
#define NSTAGE 3
#define SMEM_BYTES (NSTAGE * STAGE_SZ + 1024)

__global__ __launch_bounds__(256, 2)
void gemm_mma_kernel(const float* __restrict__ task_inputs,
                     const float* __restrict__ shared_b,
                     const float* __restrict__ task_b,
                     const float* __restrict__ gate_W,
                     const float* __restrict__ gate_b)
{
    extern __shared__ char dsm[];
    __shared__ float sbias[BN];

    const int tid = threadIdx.x;
    const int warp = tid >> 5;
    const int lane = tid & 31;
    const int z = blockIdx.z;

    // ======================= gate path (z == 10) ============================
    if (z == 10) {
        float* Wg = (float*)dsm;                       // [KIN][9] padded
        const int blk = blockIdx.y * gridDim.x + blockIdx.x;   // 0..511
        #pragma unroll 1
        for (int t = 0; t < NTASKS; t++) {
            __syncthreads();
            for (int i = tid; i < KIN * 6; i += 256)
                Wg[(i / 6) * 9 + (i % 6)] = gate_W[(size_t)t * KIN * 6 + i];
            __syncthreads();

            #pragma unroll 1
            for (int w = 0; w < 4; w++) {
                const int b = blk * 32 + warp * 4 + w;
                const float* x = task_inputs + ((size_t)t * MTOK + b) * KIN;

                float s[6] = {0.f, 0.f, 0.f, 0.f, 0.f, 0.f};
                #pragma unroll
                for (int i = 0; i < 8; i++) {
                    const int k = i * 128 + lane * 4;
                    float4 xv = *(const float4*)(x + k);
                    float xa[4] = {xv.x, xv.y, xv.z, xv.w};
                    #pragma unroll
                    for (int j = 0; j < 4; j++)
                        #pragma unroll
                        for (int e = 0; e < 6; e++)
                            s[e] = fmaf(xa[j], Wg[(k + j) * 9 + e], s[e]);
                }
                #pragma unroll
                for (int off = 16; off > 0; off >>= 1)
                    #pragma unroll
                    for (int e = 0; e < 6; e++)
                        s[e] += __shfl_xor_sync(0xffffffffu, s[e], off);

                if (lane == 0) {
                    float l[6], mx = -1e30f;
                    #pragma unroll
                    for (int e = 0; e < 6; e++) { l[e] = s[e] + gate_b[t * 6 + e]; mx = fmaxf(mx, l[e]); }
                    float sum = 0.f;
                    #pragma unroll
                    for (int e = 0; e < 6; e++) { l[e] = __expf(l[e] - mx); sum += l[e]; }
                    float inv = 1.f / sum;
                    float* gp = g_G + ((size_t)t * MTOK + b) * 6;
                    #pragma unroll
                    for (int e = 0; e < 6; e++) gp[e] = l[e] * inv;
                }
            }
        }
        return;
    }

    // ======================= GEMM path (z < 10) =============================
    const uint32_t raw = smem_u32(dsm);
    const uint32_t sb = (raw + 1023u) & ~1023u;

    const int bm0 = blockIdx.y * BM;
    const int bn0 = blockIdx.x * BN;

    size_t a_base;
    const float* bias;
    __half* out;
    if (z < 4) {
        a_base = 0;                                  // shared experts: task 0
        bias = shared_b + z * NOUT;
        out = g_S + (size_t)z * MTOK * NOUT;
    } else {
        const int j = z - 4;
        a_base = (size_t)(j >> 1) * MTOK * KIN;
        bias = task_b + j * NOUT;
        out = g_T + (size_t)j * MTOK * NOUT;
    }
    const float* A = task_inputs + a_base;           // raw fp32; HW tf32-truncates
    const float* W = g_W32 + ((size_t)z * NOUT + bn0) * KIN;

    if (tid < BN) sbias[tid] = bias[bn0 + tid];

    // ---- staging: A 16KB (1024 x 16B chunks, 4/thr), B 16KB (4/thr) --------
    uint32_t a_soff[4], b_soff[4];
    const float* a_src[4];
    const float* b_src[4];
    #pragma unroll
    for (int i = 0; i < 4; i++) {
        int c = tid + 256 * i;
        int row = c >> 3, seg = c & 7;
        uint32_t so = SW128((uint32_t)(row * 128 + seg * 16));
        a_soff[i] = so;
        b_soff[i] = so;
        a_src[i] = A + (size_t)(bm0 + row) * KIN + seg * 4;
        b_src[i] = W + (size_t)row * KIN + seg * 4;
    }

    // warp tiling: 2(M) x 4(N); warp tile 64x32
    const int wm = warp & 1, wn = warp >> 1;
    const int m_base = wm * 64;
    const int n_base = wn * 32;
    const int lg = lane >> 3, r8 = lane & 7;

    uint32_t a_lbase[4];
    #pragma unroll
    for (int mf = 0; mf < 4; mf++)
        a_lbase[mf] = (uint32_t)((m_base + mf * 16 + (lg & 1) * 8 + r8) * 128 + (lg >> 1) * 16);
    uint32_t b_lbase[2];
    #pragma unroll
    for (int p = 0; p < 2; p++)
        b_lbase[p] = (uint32_t)((n_base + p * 16 + (lg >> 1) * 8 + r8) * 128 + (lg & 1) * 16);

    float acc[4][4][4];
    #pragma unroll
    for (int mf = 0; mf < 4; mf++)
        #pragma unroll
        for (int nf = 0; nf < 4; nf++)
            #pragma unroll
            for (int r = 0; r < 4; r++) acc[mf][nf][r] = 0.f;

    auto issue = [&](int kt, int s) {
        const uint32_t sa = sb + s * STAGE_SZ;
        const int ko = kt * BK;
        #pragma unroll
        for (int i = 0; i < 4; i++)
            cp_async16(sa + ST_A + a_soff[i], a_src[i] + ko);
        #pragma unroll
        for (int i = 0; i < 4; i++)
            cp_async16(sa + ST_B + b_soff[i], b_src[i] + ko);
    };

    issue(0, 0); CP_COMMIT();
    issue(1, 1); CP_COMMIT();

    int buf = 0, nxt = 2;
    #pragma unroll 1
    for (int kt = 0; kt < NKT; kt++) {
        CP_WAIT1();
        __syncthreads();

        if (kt + 2 < NKT) issue(kt + 2, nxt);
        CP_COMMIT();

        const uint32_t ab = sb + buf * STAGE_SZ;
        buf = (buf == 2) ? 0 : buf + 1;
        nxt = (nxt == 2) ? 0 : nxt + 1;

        // B-fragment double buffer: prefetch next kt4's B while doing MMAs
        uint32_t bfr[2][4][2];
        {
            #pragma unroll
            for (int p = 0; p < 2; p++) {
                uint32_t r[4];
                ldm_x4(r, ab + ST_B + SW128(b_lbase[p]));
                bfr[0][2 * p][0] = r[0];     bfr[0][2 * p][1] = r[1];
                bfr[0][2 * p + 1][0] = r[2]; bfr[0][2 * p + 1][1] = r[3];
            }
        }
        #pragma unroll
        for (int kt4 = 0; kt4 < 4; kt4++) {
            const int cur = kt4 & 1;
            if (kt4 < 3) {
                const int nx = cur ^ 1;
                #pragma unroll
                for (int p = 0; p < 2; p++) {
                    uint32_t r[4];
                    ldm_x4(r, ab + ST_B + SW128(b_lbase[p] + (kt4 + 1) * 32));
                    bfr[nx][2 * p][0] = r[0];     bfr[nx][2 * p][1] = r[1];
                    bfr[nx][2 * p + 1][0] = r[2]; bfr[nx][2 * p + 1][1] = r[3];
                }
            }
            #pragma unroll
            for (int mf = 0; mf < 4; mf++) {
                uint32_t afr[4];
                ldm_x4(afr, ab + ST_A + SW128(a_lbase[mf] + kt4 * 32));
                #pragma unroll
                for (int nf = 0; nf < 4; nf++)
                    mma_tf32(acc[mf][nf], afr, bfr[cur][nf]);
            }
        }
    }

    // ---- epilogue: bias + relu + fp16 store ----
    const int gq = lane >> 2, i2 = (lane & 3) * 2;
    #pragma unroll
    for (int mf = 0; mf < 4; mf++) {
        const int r0 = bm0 + m_base + mf * 16 + gq;
        #pragma unroll
        for (int nf = 0; nf < 4; nf++) {
            const int cl = n_base + nf * 8 + i2;
            const float b0 = sbias[cl], b1 = sbias[cl + 1];
            __half2 v0 = __floats2half2_rn(fmaxf(acc[mf][nf][0] + b0, 0.f),
                                           fmaxf(acc[mf][nf][1] + b1, 0.f));
            __half2 v1 = __floats2half2_rn(fmaxf(acc[mf][nf][2] + b0, 0.f),
                                           fmaxf(acc[mf][nf][3] + b1, 0.f));
            *(__half2*)(out + (size_t)r0 * NOUT + bn0 + cl) = v0;
            *(__half2*)(out + (size_t)(r0 + 8) * NOUT + bn0 + cl) = v1;
        }
    }
}

// ---------------- combine: all 3 tasks per thread (S read once, fp16 in) -----
__global__ __launch_bounds__(256)
void combine_kernel(float* __restrict__ out)
{
    const size_t idx = (size_t)blockIdx.x * 256 + threadIdx.x;   // b*128 + o4
    const int o4 = (int)(idx & (NOUT / 4 - 1));                  // 0..127
    const int b = (int)(idx >> 7);

    float ge[NTASKS][6];
    #pragma unroll
    for (int t = 0; t < NTASKS; t++) {
        const float* g = g_G + ((size_t)t * MTOK + b) * 6;
        #pragma unroll
        for (int e = 0; e < 6; e++) ge[t][e] = g[e];
    }

    float4 r[NTASKS];
    #pragma unroll
    for (int t = 0; t < NTASKS; t++) r[t] = make_float4(0.f, 0.f, 0.f, 0.f);

    #pragma unroll
    for (int e = 0; e < 4; e++) {
        const __half2* sp = (const __half2*)(g_S + (((size_t)e * MTOK) + b) * NOUT + o4 * 4);
        float2 f0 = __half22float2(sp[0]);
        float2 f1 = __half22float2(sp[1]);
        #pragma unroll
        for (int t = 0; t < NTASKS; t++) {
            r[t].x = fmaf(ge[t][e], f0.x, r[t].x);
            r[t].y = fmaf(ge[t][e], f0.y, r[t].y);
            r[t].z = fmaf(ge[t][e], f1.x, r[t].z);
            r[t].w = fmaf(ge[t][e], f1.y, r[t].w);
        }
    }
    #pragma unroll
    for (int t = 0; t < NTASKS; t++) {
        #pragma unroll
        for (int e = 0; e < 2; e++) {
            const __half2* sp = (const __half2*)(g_T + (((size_t)(t * 2 + e) * MTOK) + b) * NOUT + o4 * 4);
            float2 f0 = __half22float2(sp[0]);
            float2 f1 = __half22float2(sp[1]);
            r[t].x = fmaf(ge[t][4 + e], f0.x, r[t].x);
            r[t].y = fmaf(ge[t][4 + e], f0.y, r[t].y);
            r[t].z = fmaf(ge[t][4 + e], f1.x, r[t].z);
            r[t].w = fmaf(ge[t][4 + e], f1.y, r[t].w);
        }
        *(float4*)(out + (((size_t)t * MTOK + b) * NOUT) + o4 * 4) = r[t];
    }
}

// ---------------- launch -----------------------------------------------------
extern "C" void kernel_launch(void* const* d_in, const int* in_sizes, int n_in,
                              void* d_out, int out_size)
{
    const float* task_inputs = (const float*)d_in[0];
    const float* shared_W    = (const float*)d_in[1];
    const float* shared_b    = (const float*)d_in[2];
    const float* task_W      = (const float*)d_in[3];
    const float* task_b      = (const float*)d_in[4];
    const float* gate_W      = (const float*)d_in[5];
    const float* gate_b      = (const float*)d_in[6];
    float* out = (float*)d_out;

    cudaFuncSetAttribute(gemm_mma_kernel,
                         cudaFuncAttributeMaxDynamicSharedMemorySize, SMEM_BYTES);

    // 1) W transpose + tf32 rounding
    wprep_kernel<<<dim3(KIN / 32, NOUT / 32, NEXP), 256>>>(shared_W, task_W);

    // 2) fused: 10 expert GEMMs (z<10) + gates (z==10)
    gemm_mma_kernel<<<dim3(NOUT / BN, MTOK / BM, NEXP + 1), 256, SMEM_BYTES>>>(
        task_inputs, shared_b, task_b, gate_W, gate_b);

    // 3) gated combine (fp16 expert outs, all 3 tasks per thread)
    const size_t totalc = (size_t)MTOK * (NOUT / 4);
    combine_kernel<<<(unsigned)(totalc / 256), 256>>>(out);
}